// round 2
// baseline (speedup 1.0000x reference)
#include <cuda_runtime.h>
#include <math.h>

#define EMBED 1024
#define HEADS 16
#define HD 64
#define MLP_DIM 4096
#define BATCH 8
#define SEQ 1024
#define ROWS (BATCH * SEQ)   // 8192

// ---------------- scratch (device globals: no allocation allowed) -----------
__device__ float g_h[ROWS * EMBED];        //  32 MB  (LN outputs)
__device__ float g_qkv[ROWS * 3 * EMBED];  // 100 MB
__device__ float g_attn[ROWS * EMBED];     //  32 MB
__device__ float g_fc1[ROWS * MLP_DIM];    // 134 MB

// ---------------- LayerNorm: one block per row ------------------------------
__global__ __launch_bounds__(256) void ln_kernel(
    const float* __restrict__ x, const float* __restrict__ g,
    const float* __restrict__ b, float* __restrict__ out)
{
    int row = blockIdx.x;
    int t = threadIdx.x;
    const float4* xr = reinterpret_cast<const float4*>(x + (size_t)row * EMBED);
    float4 v = xr[t];
    float s  = v.x + v.y + v.z + v.w;
    float ss = v.x * v.x + v.y * v.y + v.z * v.z + v.w * v.w;
    #pragma unroll
    for (int o = 16; o > 0; o >>= 1) {
        s  += __shfl_xor_sync(0xffffffffu, s,  o);
        ss += __shfl_xor_sync(0xffffffffu, ss, o);
    }
    __shared__ float sm[8], sm2[8];
    int w = t >> 5, l = t & 31;
    if (l == 0) { sm[w] = s; sm2[w] = ss; }
    __syncthreads();
    float tot = 0.f, tot2 = 0.f;
    #pragma unroll
    for (int i = 0; i < 8; i++) { tot += sm[i]; tot2 += sm2[i]; }
    float mu   = tot * (1.0f / EMBED);
    float var  = tot2 * (1.0f / EMBED) - mu * mu;
    float rstd = rsqrtf(var + 1e-5f);
    float4 gg = reinterpret_cast<const float4*>(g)[t];
    float4 bb = reinterpret_cast<const float4*>(b)[t];
    float4 o;
    o.x = (v.x - mu) * rstd * gg.x + bb.x;
    o.y = (v.y - mu) * rstd * gg.y + bb.y;
    o.z = (v.z - mu) * rstd * gg.z + bb.z;
    o.w = (v.w - mu) * rstd * gg.w + bb.w;
    reinterpret_cast<float4*>(out + (size_t)row * EMBED)[t] = o;
}

// ---------------- SGEMM: C = A[MxK] * B[KxN] + bias (+res / gelu) -----------
// MODE 0: +bias  |  MODE 1: +bias+residual  |  MODE 2: +bias, GELU(exact)
template <int MODE>
__global__ __launch_bounds__(256) void sgemm_kernel(
    int M, int N, int K,
    const float* __restrict__ A, const float* __restrict__ B,
    const float* __restrict__ bias, const float* __restrict__ res,
    float* __restrict__ C)
{
    const int BM = 128, BN = 128, BK = 8;
    __shared__ float As[BK][BM];
    __shared__ float Bs[BK][BN];

    int tid = threadIdx.x;
    int m0 = blockIdx.y * BM;
    int n0 = blockIdx.x * BN;
    int tr = tid / 16;          // 0..15
    int tc = tid % 16;          // 0..15

    float acc[8][8];
    #pragma unroll
    for (int i = 0; i < 8; i++)
        #pragma unroll
        for (int j = 0; j < 8; j++) acc[i][j] = 0.f;

    int aRow = tid >> 1;            // 0..127
    int aCol = (tid & 1) * 4;       // 0 or 4
    int bRow = tid >> 5;            // 0..7
    int bCol = (tid & 31) * 4;      // 0..124

    const float* Ag = A + (size_t)(m0 + aRow) * K + aCol;
    const float* Bg = B + (size_t)bRow * N + n0 + bCol;

    for (int k0 = 0; k0 < K; k0 += BK) {
        float4 a = *reinterpret_cast<const float4*>(Ag + k0);
        As[aCol + 0][aRow] = a.x;
        As[aCol + 1][aRow] = a.y;
        As[aCol + 2][aRow] = a.z;
        As[aCol + 3][aRow] = a.w;
        float4 bv = *reinterpret_cast<const float4*>(Bg + (size_t)k0 * N);
        *reinterpret_cast<float4*>(&Bs[bRow][bCol]) = bv;
        __syncthreads();

        #pragma unroll
        for (int k = 0; k < BK; k++) {
            float4 a0 = *reinterpret_cast<const float4*>(&As[k][tr * 8]);
            float4 a1 = *reinterpret_cast<const float4*>(&As[k][tr * 8 + 4]);
            float4 b0 = *reinterpret_cast<const float4*>(&Bs[k][tc * 8]);
            float4 b1 = *reinterpret_cast<const float4*>(&Bs[k][tc * 8 + 4]);
            float ar[8] = {a0.x, a0.y, a0.z, a0.w, a1.x, a1.y, a1.z, a1.w};
            float br[8] = {b0.x, b0.y, b0.z, b0.w, b1.x, b1.y, b1.z, b1.w};
            #pragma unroll
            for (int i = 0; i < 8; i++)
                #pragma unroll
                for (int j = 0; j < 8; j++)
                    acc[i][j] += ar[i] * br[j];
        }
        __syncthreads();
    }

    // epilogue
    float bi[8];
    {
        float4 b0 = *reinterpret_cast<const float4*>(&bias[n0 + tc * 8]);
        float4 b1 = *reinterpret_cast<const float4*>(&bias[n0 + tc * 8 + 4]);
        bi[0] = b0.x; bi[1] = b0.y; bi[2] = b0.z; bi[3] = b0.w;
        bi[4] = b1.x; bi[5] = b1.y; bi[6] = b1.z; bi[7] = b1.w;
    }
    #pragma unroll
    for (int i = 0; i < 8; i++) {
        int row = m0 + tr * 8 + i;
        size_t off = (size_t)row * N + n0 + tc * 8;
        float o[8];
        #pragma unroll
        for (int j = 0; j < 8; j++) o[j] = acc[i][j] + bi[j];
        if (MODE == 1) {
            float4 r0 = *reinterpret_cast<const float4*>(&res[off]);
            float4 r1 = *reinterpret_cast<const float4*>(&res[off + 4]);
            o[0] += r0.x; o[1] += r0.y; o[2] += r0.z; o[3] += r0.w;
            o[4] += r1.x; o[5] += r1.y; o[6] += r1.z; o[7] += r1.w;
        }
        if (MODE == 2) {
            #pragma unroll
            for (int j = 0; j < 8; j++)
                o[j] = 0.5f * o[j] * (1.0f + erff(o[j] * 0.70710678118654752f));
        }
        *reinterpret_cast<float4*>(&C[off])     = make_float4(o[0], o[1], o[2], o[3]);
        *reinterpret_cast<float4*>(&C[off + 4]) = make_float4(o[4], o[5], o[6], o[7]);
    }
}

// ---------------- Flash attention (fp32, online softmax) --------------------
// grid: (B*H, SEQ/64); block: 256 threads.
// Each block: one (b,h), 64 Q rows.  Thread t: rows rg=t>>3 and rg+32; lane
// group q8=t&7 partitions the j (score cols) and d (output dims) dimensions.
__global__ __launch_bounds__(256) void flash_kernel(
    const float* __restrict__ qkv, float* __restrict__ out)
{
    const int KT = 32;
    __shared__ float Qs[64][65];
    __shared__ float Ks[KT][65];
    __shared__ float Vs[KT][65];
    __shared__ float Ps[64][33];

    int b = blockIdx.x >> 4;
    int h = blockIdx.x & 15;
    int q0 = blockIdx.y * 64;
    int t = threadIdx.x;
    int rg = t >> 3;     // 0..31
    int q8 = t & 7;      // 0..7

    const float* base = qkv + (size_t)b * SEQ * (3 * EMBED) + h * HD;

    for (int i = t; i < 64 * 64; i += 256) {
        int rr = i >> 6, dd = i & 63;
        Qs[rr][dd] = base[(size_t)(q0 + rr) * (3 * EMBED) + dd] * 0.125f;
    }

    float m0v = -1e30f, m1v = -1e30f, l0v = 0.f, l1v = 0.f;
    float acc0[8], acc1[8];
    #pragma unroll
    for (int i = 0; i < 8; i++) { acc0[i] = 0.f; acc1[i] = 0.f; }
    __syncthreads();

    for (int kt = 0; kt < SEQ; kt += KT) {
        for (int i = t; i < KT * 64; i += 256) {
            int rr = i >> 6, dd = i & 63;
            const float* kb = base + (size_t)(kt + rr) * (3 * EMBED) + dd;
            Ks[rr][dd] = kb[EMBED];
            Vs[rr][dd] = kb[2 * EMBED];
        }
        __syncthreads();

        // scores: s[jj] for j = q8 + 8*jj (2 q-rows per thread)
        float s0[4] = {0.f, 0.f, 0.f, 0.f};
        float s1[4] = {0.f, 0.f, 0.f, 0.f};
        #pragma unroll
        for (int d = 0; d < 64; d++) {
            float qa = Qs[rg][d];
            float qb = Qs[rg + 32][d];
            #pragma unroll
            for (int jj = 0; jj < 4; jj++) {
                float kv = Ks[q8 + 8 * jj][d];
                s0[jj] += qa * kv;
                s1[jj] += qb * kv;
            }
        }
        float mn0 = fmaxf(fmaxf(s0[0], s0[1]), fmaxf(s0[2], s0[3]));
        float mn1 = fmaxf(fmaxf(s1[0], s1[1]), fmaxf(s1[2], s1[3]));
        #pragma unroll
        for (int o = 1; o < 8; o <<= 1) {
            mn0 = fmaxf(mn0, __shfl_xor_sync(0xffffffffu, mn0, o));
            mn1 = fmaxf(mn1, __shfl_xor_sync(0xffffffffu, mn1, o));
        }
        mn0 = fmaxf(m0v, mn0);
        mn1 = fmaxf(m1v, mn1);
        float c0 = __expf(m0v - mn0);
        float c1 = __expf(m1v - mn1);
        float ls0 = 0.f, ls1 = 0.f;
        #pragma unroll
        for (int jj = 0; jj < 4; jj++) {
            float p0 = __expf(s0[jj] - mn0);
            float p1 = __expf(s1[jj] - mn1);
            Ps[rg][q8 + 8 * jj] = p0;
            Ps[rg + 32][q8 + 8 * jj] = p1;
            ls0 += p0;
            ls1 += p1;
        }
        #pragma unroll
        for (int o = 1; o < 8; o <<= 1) {
            ls0 += __shfl_xor_sync(0xffffffffu, ls0, o);
            ls1 += __shfl_xor_sync(0xffffffffu, ls1, o);
        }
        l0v = l0v * c0 + ls0;
        l1v = l1v * c1 + ls1;
        m0v = mn0;
        m1v = mn1;
        #pragma unroll
        for (int i = 0; i < 8; i++) { acc0[i] *= c0; acc1[i] *= c1; }
        __syncwarp();   // Ps rows rg/rg+32 are written only by this warp's 8-lane group

        #pragma unroll
        for (int j = 0; j < KT; j++) {
            float pa = Ps[rg][j];
            float pb = Ps[rg + 32][j];
            #pragma unroll
            for (int dd = 0; dd < 8; dd++) {
                float v = Vs[j][q8 + 8 * dd];
                acc0[dd] += pa * v;
                acc1[dd] += pb * v;
            }
        }
        __syncthreads();
    }

    float inv0 = 1.f / l0v;
    float inv1 = 1.f / l1v;
    float* o0 = out + (size_t)(b * SEQ + q0 + rg) * EMBED + h * HD;
    float* o1 = o0 + (size_t)32 * EMBED;
    #pragma unroll
    for (int dd = 0; dd < 8; dd++) {
        o0[q8 + 8 * dd] = acc0[dd] * inv0;
        o1[q8 + 8 * dd] = acc1[dd] * inv1;
    }
}

// ---------------- launcher ---------------------------------------------------
extern "C" void kernel_launch(void* const* d_in, const int* in_sizes, int n_in,
                              void* d_out, int out_size)
{
    const float* x      = (const float*)d_in[0];
    const float* ln1_g  = (const float*)d_in[1];
    const float* ln1_b  = (const float*)d_in[2];
    const float* w_qkv  = (const float*)d_in[3];
    const float* b_qkv  = (const float*)d_in[4];
    const float* w_proj = (const float*)d_in[5];
    const float* b_proj = (const float*)d_in[6];
    const float* ln2_g  = (const float*)d_in[7];
    const float* ln2_b  = (const float*)d_in[8];
    const float* w_fc1  = (const float*)d_in[9];
    const float* b_fc1  = (const float*)d_in[10];
    const float* w_fc2  = (const float*)d_in[11];
    const float* b_fc2  = (const float*)d_in[12];
    float* out = (float*)d_out;

    float *h, *qkv, *attn, *fc1;
    cudaGetSymbolAddress((void**)&h,    g_h);
    cudaGetSymbolAddress((void**)&qkv,  g_qkv);
    cudaGetSymbolAddress((void**)&attn, g_attn);
    cudaGetSymbolAddress((void**)&fc1,  g_fc1);

    // 1) LN1: x -> h
    ln_kernel<<<ROWS, 256>>>(x, ln1_g, ln1_b, h);

    // 2) QKV GEMM: h[8192,1024] @ w_qkv[1024,3072] + b_qkv -> qkv
    sgemm_kernel<0><<<dim3(3 * EMBED / 128, ROWS / 128), 256>>>(
        ROWS, 3 * EMBED, EMBED, h, w_qkv, b_qkv, nullptr, qkv);

    // 3) attention -> attn
    flash_kernel<<<dim3(BATCH * HEADS, SEQ / 64), 256>>>(qkv, attn);

    // 4) proj + residual(x) -> out  (out now holds x1)
    sgemm_kernel<1><<<dim3(EMBED / 128, ROWS / 128), 256>>>(
        ROWS, EMBED, EMBED, attn, w_proj, b_proj, x, out);

    // 5) LN2: out -> h
    ln_kernel<<<ROWS, 256>>>(out, ln2_g, ln2_b, h);

    // 6) FC1 + GELU: h @ w_fc1[1024,4096] -> fc1
    sgemm_kernel<2><<<dim3(MLP_DIM / 128, ROWS / 128), 256>>>(
        ROWS, MLP_DIM, EMBED, h, w_fc1, b_fc1, nullptr, fc1);

    // 7) FC2 + residual(out) -> out (in-place elementwise safe: each element
    //    read then written by exactly one thread)
    sgemm_kernel<1><<<dim3(EMBED / 128, ROWS / 128), 256>>>(
        ROWS, EMBED, MLP_DIM, fc1, w_fc2, b_fc2, out, out);
}

// round 4
// speedup vs baseline: 1.3754x; 1.3754x over previous
#include <cuda_runtime.h>
#include <math.h>
#include <stdint.h>

#define EMBED 1024
#define HEADS 16
#define HD 64
#define MLP_DIM 4096
#define BATCH 8
#define SEQ 1024
#define ROWS (BATCH * SEQ)   // 8192

// ---------------- scratch (device globals: no allocation allowed) -----------
__device__ float g_h[ROWS * EMBED];          //  32 MB  (LN outputs)
__device__ float g_qkv[ROWS * 3 * EMBED];    // 100 MB
__device__ float g_attn[ROWS * EMBED];       //  32 MB
__device__ float g_fc1[ROWS * MLP_DIM];      // 134 MB
__device__ float g_wt[12582912];             //  50 MB  (transposed weights)

#define WT_QKV  0
#define WT_PROJ (3 * EMBED * EMBED)
#define WT_FC1  (WT_PROJ + EMBED * EMBED)
#define WT_FC2  (WT_FC1 + EMBED * MLP_DIM)

__device__ __forceinline__ float tf32r(float x) {
    uint32_t o;
    asm("cvt.rna.tf32.f32 %0, %1;" : "=r"(o) : "f"(x));
    return __uint_as_float(o);
}

// ---------------- weight transpose: out[N,K] = in[K,N]^T --------------------
__global__ __launch_bounds__(256) void transpose_kernel(
    const float* __restrict__ in, float* __restrict__ out, int K, int N)
{
    __shared__ float tile[32][33];
    int n0 = blockIdx.x * 32, k0 = blockIdx.y * 32;
    int tx = threadIdx.x, ty = threadIdx.y;   // 32 x 8
    #pragma unroll
    for (int i = 0; i < 32; i += 8)
        tile[ty + i][tx] = in[(size_t)(k0 + ty + i) * N + n0 + tx];
    __syncthreads();
    #pragma unroll
    for (int i = 0; i < 32; i += 8)
        out[(size_t)(n0 + ty + i) * K + k0 + tx] = tile[tx][ty + i];
}

// ---------------- tf32 mma.sync GEMM: C = A[M,K] @ WT[N,K]^T ----------------
// CTA tile 128x128, BK=32, 8 warps (2 M x 4 N), warp tile 64x32, m16n8k8 atoms.
// MODE 0: +bias | MODE 1: +bias+residual | MODE 2: +bias, exact GELU
// SMEM rows padded to 36 floats -> fragment LDS are conflict-free and
// float4 cp targets stay 16B aligned.
#define LDPAD 36
#define STG_F (128 * LDPAD)          // floats per tile buffer (4608)

template <int MODE>
__global__ __launch_bounds__(256) void tgemm(
    const float* __restrict__ A, const float* __restrict__ WT,
    const float* __restrict__ bias, const float* __restrict__ res,
    float* __restrict__ C, int N, int K)
{
    extern __shared__ float smf[];    // [2 x A(4608)] [2 x B(4608)] = 73728 B
    const int t = threadIdx.x;
    const int warp = t >> 5, lane = t & 31;
    const int lr = lane >> 2, lc = lane & 3;
    const int wm = warp >> 2, wn = warp & 3;       // 2 x 4
    const int m0 = blockIdx.y << 7;
    const int n0 = blockIdx.x << 7;

    float acc[4][4][4];
    #pragma unroll
    for (int m = 0; m < 4; m++)
        #pragma unroll
        for (int n = 0; n < 4; n++)
            #pragma unroll
            for (int r = 0; r < 4; r++) acc[m][n][r] = 0.f;

    // loader geometry: thread t covers rows r0+32*i (i<4), k-quad kq (constant)
    const int r0 = t >> 3;            // 0..31
    const int kq = t & 7;             // 0..7  -> floats kq*4..kq*4+3
    const float* Ag = A  + (size_t)(m0 + r0) * K + (kq << 2);
    const float* Bg = WT + (size_t)(n0 + r0) * K + (kq << 2);
    const int sts_base = r0 * LDPAD + (kq << 2);

    const int S = K >> 5;

    // prologue: fill buffer 0
    {
        #pragma unroll
        for (int i = 0; i < 4; i++) {
            float4 va = *reinterpret_cast<const float4*>(Ag + (size_t)(i << 5) * K);
            float4 vb = *reinterpret_cast<const float4*>(Bg + (size_t)(i << 5) * K);
            float* da = smf + sts_base + i * (32 * LDPAD);
            float* db = smf + 2 * STG_F + sts_base + i * (32 * LDPAD);
            da[0] = tf32r(va.x); da[1] = tf32r(va.y); da[2] = tf32r(va.z); da[3] = tf32r(va.w);
            db[0] = tf32r(vb.x); db[1] = tf32r(vb.y); db[2] = tf32r(vb.z); db[3] = tf32r(vb.w);
        }
    }
    __syncthreads();

    for (int s = 0; s < S; s++) {
        // prefetch next K-slab into registers (overlaps with compute)
        float4 pa[4], pb[4];
        if (s + 1 < S) {
            int kc = (s + 1) << 5;
            #pragma unroll
            for (int i = 0; i < 4; i++) {
                pa[i] = *reinterpret_cast<const float4*>(Ag + (size_t)(i << 5) * K + kc);
                pb[i] = *reinterpret_cast<const float4*>(Bg + (size_t)(i << 5) * K + kc);
            }
        }

        // compute on buffer s&1
        {
            const float* As = smf + (s & 1) * STG_F;
            const float* Bs = smf + 2 * STG_F + (s & 1) * STG_F;
            #pragma unroll
            for (int kk = 0; kk < 4; kk++) {
                uint32_t a[4][4], b[4][2];
                #pragma unroll
                for (int m = 0; m < 4; m++) {
                    const float* p = As + (wm * 64 + m * 16 + lr) * LDPAD + (kk << 3) + lc;
                    a[m][0] = __float_as_uint(p[0]);
                    a[m][1] = __float_as_uint(p[8 * LDPAD]);
                    a[m][2] = __float_as_uint(p[4]);
                    a[m][3] = __float_as_uint(p[8 * LDPAD + 4]);
                }
                #pragma unroll
                for (int n = 0; n < 4; n++) {
                    const float* p = Bs + (wn * 32 + n * 8 + lr) * LDPAD + (kk << 3) + lc;
                    b[n][0] = __float_as_uint(p[0]);
                    b[n][1] = __float_as_uint(p[4]);
                }
                #pragma unroll
                for (int m = 0; m < 4; m++)
                    #pragma unroll
                    for (int n = 0; n < 4; n++)
                        asm volatile(
                            "mma.sync.aligned.m16n8k8.row.col.f32.tf32.tf32.f32 "
                            "{%0,%1,%2,%3}, {%4,%5,%6,%7}, {%8,%9}, {%0,%1,%2,%3};"
                            : "+f"(acc[m][n][0]), "+f"(acc[m][n][1]),
                              "+f"(acc[m][n][2]), "+f"(acc[m][n][3])
                            : "r"(a[m][0]), "r"(a[m][1]), "r"(a[m][2]), "r"(a[m][3]),
                              "r"(b[n][0]), "r"(b[n][1]));
            }
        }

        // store prefetched slab into the other buffer
        if (s + 1 < S) {
            float* da = smf + ((s + 1) & 1) * STG_F + sts_base;
            float* db = smf + 2 * STG_F + ((s + 1) & 1) * STG_F + sts_base;
            #pragma unroll
            for (int i = 0; i < 4; i++) {
                float* qa = da + i * (32 * LDPAD);
                float* qb = db + i * (32 * LDPAD);
                qa[0] = tf32r(pa[i].x); qa[1] = tf32r(pa[i].y);
                qa[2] = tf32r(pa[i].z); qa[3] = tf32r(pa[i].w);
                qb[0] = tf32r(pb[i].x); qb[1] = tf32r(pb[i].y);
                qb[2] = tf32r(pb[i].z); qb[3] = tf32r(pb[i].w);
            }
        }
        __syncthreads();
    }

    // ---------------- epilogue ----------------
    const int rb = m0 + wm * 64;
    const int cb = n0 + wn * 32;
    #pragma unroll
    for (int m = 0; m < 4; m++) {
        #pragma unroll
        for (int n = 0; n < 4; n++) {
            int r  = rb + m * 16 + lr;
            int c  = cb + n * 8 + lc * 2;
            float2 bv = *reinterpret_cast<const float2*>(bias + c);
            #pragma unroll
            for (int half = 0; half < 2; half++) {
                int rr = r + half * 8;
                float o0 = acc[m][n][2 * half + 0] + bv.x;
                float o1 = acc[m][n][2 * half + 1] + bv.y;
                size_t off = (size_t)rr * N + c;
                if (MODE == 1) {
                    float2 rv = *reinterpret_cast<const float2*>(res + off);
                    o0 += rv.x; o1 += rv.y;
                }
                if (MODE == 2) {
                    o0 = 0.5f * o0 * (1.0f + erff(o0 * 0.70710678118654752f));
                    o1 = 0.5f * o1 * (1.0f + erff(o1 * 0.70710678118654752f));
                }
                *reinterpret_cast<float2*>(C + off) = make_float2(o0, o1);
            }
        }
    }
}

#define TGEMM_SMEM (4 * STG_F * 4)   // 73728 bytes

// ---------------- LayerNorm: one block per row ------------------------------
__global__ __launch_bounds__(256) void ln_kernel(
    const float* __restrict__ x, const float* __restrict__ g,
    const float* __restrict__ b, float* __restrict__ out)
{
    int row = blockIdx.x;
    int t = threadIdx.x;
    const float4* xr = reinterpret_cast<const float4*>(x + (size_t)row * EMBED);
    float4 v = xr[t];
    float s  = v.x + v.y + v.z + v.w;
    float ss = v.x * v.x + v.y * v.y + v.z * v.z + v.w * v.w;
    #pragma unroll
    for (int o = 16; o > 0; o >>= 1) {
        s  += __shfl_xor_sync(0xffffffffu, s,  o);
        ss += __shfl_xor_sync(0xffffffffu, ss, o);
    }
    __shared__ float sm[8], sm2[8];
    int w = t >> 5, l = t & 31;
    if (l == 0) { sm[w] = s; sm2[w] = ss; }
    __syncthreads();
    float tot = 0.f, tot2 = 0.f;
    #pragma unroll
    for (int i = 0; i < 8; i++) { tot += sm[i]; tot2 += sm2[i]; }
    float mu   = tot * (1.0f / EMBED);
    float var  = tot2 * (1.0f / EMBED) - mu * mu;
    float rstd = rsqrtf(var + 1e-5f);
    float4 gg = reinterpret_cast<const float4*>(g)[t];
    float4 bb = reinterpret_cast<const float4*>(b)[t];
    float4 o;
    o.x = (v.x - mu) * rstd * gg.x + bb.x;
    o.y = (v.y - mu) * rstd * gg.y + bb.y;
    o.z = (v.z - mu) * rstd * gg.z + bb.z;
    o.w = (v.w - mu) * rstd * gg.w + bb.w;
    reinterpret_cast<float4*>(out + (size_t)row * EMBED)[t] = o;
}

// ---------------- Flash attention (fp32, online softmax) --------------------
__global__ __launch_bounds__(256) void flash_kernel(
    const float* __restrict__ qkv, float* __restrict__ out)
{
    const int KT = 32;
    __shared__ float Qs[64][65];
    __shared__ float Ks[KT][65];
    __shared__ float Vs[KT][65];
    __shared__ float Ps[64][33];

    int b = blockIdx.x >> 4;
    int h = blockIdx.x & 15;
    int q0 = blockIdx.y * 64;
    int t = threadIdx.x;
    int rg = t >> 3;     // 0..31
    int q8 = t & 7;      // 0..7

    const float* base = qkv + (size_t)b * SEQ * (3 * EMBED) + h * HD;

    for (int i = t; i < 64 * 64; i += 256) {
        int rr = i >> 6, dd = i & 63;
        Qs[rr][dd] = base[(size_t)(q0 + rr) * (3 * EMBED) + dd] * 0.125f;
    }

    float m0v = -1e30f, m1v = -1e30f, l0v = 0.f, l1v = 0.f;
    float acc0[8], acc1[8];
    #pragma unroll
    for (int i = 0; i < 8; i++) { acc0[i] = 0.f; acc1[i] = 0.f; }
    __syncthreads();

    for (int kt = 0; kt < SEQ; kt += KT) {
        for (int i = t; i < KT * 64; i += 256) {
            int rr = i >> 6, dd = i & 63;
            const float* kb = base + (size_t)(kt + rr) * (3 * EMBED) + dd;
            Ks[rr][dd] = kb[EMBED];
            Vs[rr][dd] = kb[2 * EMBED];
        }
        __syncthreads();

        float s0[4] = {0.f, 0.f, 0.f, 0.f};
        float s1[4] = {0.f, 0.f, 0.f, 0.f};
        #pragma unroll
        for (int d = 0; d < 64; d++) {
            float qa = Qs[rg][d];
            float qb = Qs[rg + 32][d];
            #pragma unroll
            for (int jj = 0; jj < 4; jj++) {
                float kv = Ks[q8 + 8 * jj][d];
                s0[jj] += qa * kv;
                s1[jj] += qb * kv;
            }
        }
        float mn0 = fmaxf(fmaxf(s0[0], s0[1]), fmaxf(s0[2], s0[3]));
        float mn1 = fmaxf(fmaxf(s1[0], s1[1]), fmaxf(s1[2], s1[3]));
        #pragma unroll
        for (int o = 1; o < 8; o <<= 1) {
            mn0 = fmaxf(mn0, __shfl_xor_sync(0xffffffffu, mn0, o));
            mn1 = fmaxf(mn1, __shfl_xor_sync(0xffffffffu, mn1, o));
        }
        mn0 = fmaxf(m0v, mn0);
        mn1 = fmaxf(m1v, mn1);
        float c0 = __expf(m0v - mn0);
        float c1 = __expf(m1v - mn1);
        float ls0 = 0.f, ls1 = 0.f;
        #pragma unroll
        for (int jj = 0; jj < 4; jj++) {
            float p0 = __expf(s0[jj] - mn0);
            float p1 = __expf(s1[jj] - mn1);
            Ps[rg][q8 + 8 * jj] = p0;
            Ps[rg + 32][q8 + 8 * jj] = p1;
            ls0 += p0;
            ls1 += p1;
        }
        #pragma unroll
        for (int o = 1; o < 8; o <<= 1) {
            ls0 += __shfl_xor_sync(0xffffffffu, ls0, o);
            ls1 += __shfl_xor_sync(0xffffffffu, ls1, o);
        }
        l0v = l0v * c0 + ls0;
        l1v = l1v * c1 + ls1;
        m0v = mn0;
        m1v = mn1;
        #pragma unroll
        for (int i = 0; i < 8; i++) { acc0[i] *= c0; acc1[i] *= c1; }
        __syncwarp();

        #pragma unroll
        for (int j = 0; j < KT; j++) {
            float pa = Ps[rg][j];
            float pb = Ps[rg + 32][j];
            #pragma unroll
            for (int dd = 0; dd < 8; dd++) {
                float v = Vs[j][q8 + 8 * dd];
                acc0[dd] += pa * v;
                acc1[dd] += pb * v;
            }
        }
        __syncthreads();
    }

    float inv0 = 1.f / l0v;
    float inv1 = 1.f / l1v;
    float* o0 = out + (size_t)(b * SEQ + q0 + rg) * EMBED + h * HD;
    float* o1 = o0 + (size_t)32 * EMBED;
    #pragma unroll
    for (int dd = 0; dd < 8; dd++) {
        o0[q8 + 8 * dd] = acc0[dd] * inv0;
        o1[q8 + 8 * dd] = acc1[dd] * inv1;
    }
}

// ---------------- launcher ---------------------------------------------------
extern "C" void kernel_launch(void* const* d_in, const int* in_sizes, int n_in,
                              void* d_out, int out_size)
{
    const float* x      = (const float*)d_in[0];
    const float* ln1_g  = (const float*)d_in[1];
    const float* ln1_b  = (const float*)d_in[2];
    const float* w_qkv  = (const float*)d_in[3];
    const float* b_qkv  = (const float*)d_in[4];
    const float* w_proj = (const float*)d_in[5];
    const float* b_proj = (const float*)d_in[6];
    const float* ln2_g  = (const float*)d_in[7];
    const float* ln2_b  = (const float*)d_in[8];
    const float* w_fc1  = (const float*)d_in[9];
    const float* b_fc1  = (const float*)d_in[10];
    const float* w_fc2  = (const float*)d_in[11];
    const float* b_fc2  = (const float*)d_in[12];
    float* out = (float*)d_out;

    float *h, *qkv, *attn, *fc1, *wt;
    cudaGetSymbolAddress((void**)&h,    g_h);
    cudaGetSymbolAddress((void**)&qkv,  g_qkv);
    cudaGetSymbolAddress((void**)&attn, g_attn);
    cudaGetSymbolAddress((void**)&fc1,  g_fc1);
    cudaGetSymbolAddress((void**)&wt,   g_wt);

    cudaFuncSetAttribute(tgemm<0>, cudaFuncAttributeMaxDynamicSharedMemorySize, TGEMM_SMEM);
    cudaFuncSetAttribute(tgemm<1>, cudaFuncAttributeMaxDynamicSharedMemorySize, TGEMM_SMEM);
    cudaFuncSetAttribute(tgemm<2>, cudaFuncAttributeMaxDynamicSharedMemorySize, TGEMM_SMEM);

    float* qkvT  = wt + WT_QKV;
    float* projT = wt + WT_PROJ;
    float* fc1T  = wt + WT_FC1;
    float* fc2T  = wt + WT_FC2;

    // 0) transpose weights to [N, K] (K-major => col-major B for mma)
    transpose_kernel<<<dim3(3 * EMBED / 32, EMBED / 32),   dim3(32, 8)>>>(w_qkv,  qkvT,  EMBED,   3 * EMBED);
    transpose_kernel<<<dim3(EMBED / 32,     EMBED / 32),   dim3(32, 8)>>>(w_proj, projT, EMBED,   EMBED);
    transpose_kernel<<<dim3(MLP_DIM / 32,   EMBED / 32),   dim3(32, 8)>>>(w_fc1,  fc1T,  EMBED,   MLP_DIM);
    transpose_kernel<<<dim3(EMBED / 32,     MLP_DIM / 32), dim3(32, 8)>>>(w_fc2,  fc2T,  MLP_DIM, EMBED);

    // 1) LN1: x -> h
    ln_kernel<<<ROWS, 256>>>(x, ln1_g, ln1_b, h);

    // 2) QKV GEMM: h @ w_qkv + b_qkv -> qkv
    tgemm<0><<<dim3(3 * EMBED / 128, ROWS / 128), 256, TGEMM_SMEM>>>(
        h, qkvT, b_qkv, nullptr, qkv, 3 * EMBED, EMBED);

    // 3) attention -> attn
    flash_kernel<<<dim3(BATCH * HEADS, SEQ / 64), 256>>>(qkv, attn);

    // 4) proj + residual(x) -> out
    tgemm<1><<<dim3(EMBED / 128, ROWS / 128), 256, TGEMM_SMEM>>>(
        attn, projT, b_proj, x, out, EMBED, EMBED);

    // 5) LN2: out -> h
    ln_kernel<<<ROWS, 256>>>(out, ln2_g, ln2_b, h);

    // 6) FC1 + GELU: h @ w_fc1 -> fc1
    tgemm<2><<<dim3(MLP_DIM / 128, ROWS / 128), 256, TGEMM_SMEM>>>(
        h, fc1T, b_fc1, nullptr, fc1, MLP_DIM, EMBED);

    // 7) FC2 + residual(out) -> out (in-place elementwise safe)
    tgemm<1><<<dim3(EMBED / 128, ROWS / 128), 256, TGEMM_SMEM>>>(
        fc1, fc2T, b_fc2, out, out, EMBED, MLP_DIM);
}

// round 8
// speedup vs baseline: 1.3869x; 1.0084x over previous
#include <cuda_runtime.h>
#include <math.h>
#include <stdint.h>

#define EMBED 1024
#define HEADS 16
#define HD 64
#define MLP_DIM 4096
#define BATCH 8
#define SEQ 1024
#define ROWS (BATCH * SEQ)   // 8192

// ---------------- scratch (device globals: no allocation allowed) -----------
__device__ float g_h[ROWS * EMBED];          //  32 MB  (LN outputs, tf32-rounded)
__device__ float g_qkv[ROWS * 3 * EMBED];    // 100 MB
__device__ float g_attn[ROWS * EMBED];       //  32 MB (tf32-rounded)
__device__ float g_fc1[ROWS * MLP_DIM];      // 134 MB (tf32-rounded)
__device__ float g_wt[12582912];             //  50 MB (transposed, tf32-rounded)

#define WT_QKV  0
#define WT_PROJ (3 * EMBED * EMBED)
#define WT_FC1  (WT_PROJ + EMBED * EMBED)
#define WT_FC2  (WT_FC1 + EMBED * MLP_DIM)

__device__ __forceinline__ float tf32r(float x) {
    uint32_t o;
    asm("cvt.rna.tf32.f32 %0, %1;" : "=r"(o) : "f"(x));
    return __uint_as_float(o);
}

__device__ __forceinline__ void cp16(uint32_t dst, const void* src) {
    asm volatile("cp.async.cg.shared.global [%0], [%1], 16;"
                 :: "r"(dst), "l"(src) : "memory");
}
#define CP_COMMIT() asm volatile("cp.async.commit_group;" ::: "memory")
#define CP_WAIT(n)  asm volatile("cp.async.wait_group %0;" :: "n"(n) : "memory")

// ---------------- weight transpose: out[N,K] = tf32(in[K,N]^T) --------------
__global__ __launch_bounds__(256) void transpose_kernel(
    const float* __restrict__ in, float* __restrict__ out, int K, int N)
{
    __shared__ float tile[32][33];
    int n0 = blockIdx.x * 32, k0 = blockIdx.y * 32;
    int tx = threadIdx.x, ty = threadIdx.y;   // 32 x 8
    #pragma unroll
    for (int i = 0; i < 32; i += 8)
        tile[ty + i][tx] = in[(size_t)(k0 + ty + i) * N + n0 + tx];
    __syncthreads();
    #pragma unroll
    for (int i = 0; i < 32; i += 8)
        out[(size_t)(n0 + ty + i) * K + k0 + tx] = tf32r(tile[tx][ty + i]);
}

// ---------------- tf32 mma.sync GEMM: C = A[M,K] @ WT[N,K]^T ----------------
// CTA 128x128, BK=32, 8 warps (2 M x 4 N), warp tile 64x32, m16n8k8 atoms.
// Inputs A and WT are pre-rounded to tf32 by producers -> raw cp.async copies.
// MODE 0: +bias | MODE 1: +bias+residual | MODE 2: +bias, exact GELU (tf32 out)
#define LDPAD 36
#define STG_F (128 * LDPAD)              // floats per tile buffer (4608)
#define STG_B (STG_F * 4)                // bytes per tile buffer (18432)
#define TGEMM_SMEM (4 * STG_B)           // 73728 bytes

template <int MODE>
__global__ __launch_bounds__(256, 2) void tgemm(
    const float* __restrict__ A, const float* __restrict__ WT,
    const float* __restrict__ bias, const float* __restrict__ res,
    float* __restrict__ C, int N, int K)
{
    extern __shared__ float smf[];   // [A0][A1][B0][B1], each STG_F floats
    const int t = threadIdx.x;
    const int warp = t >> 5, lane = t & 31;
    const int lr = lane >> 2, lc = lane & 3;
    const int wm = warp >> 2, wn = warp & 3;     // 2 x 4
    const int m0 = blockIdx.y << 7;
    const int n0 = blockIdx.x << 7;

    float acc[4][4][4];
    #pragma unroll
    for (int m = 0; m < 4; m++)
        #pragma unroll
        for (int n = 0; n < 4; n++)
            #pragma unroll
            for (int r = 0; r < 4; r++) acc[m][n][r] = 0.f;

    // loader geometry: thread t covers rows r0+32*i (i<4) at k-bytes kq*16
    const int r0 = t >> 3;           // 0..31
    const int kq = t & 7;            // 0..7
    const float* Ag = A  + (size_t)(m0 + r0) * K + (kq << 2);
    const float* Bg = WT + (size_t)(n0 + r0) * K + (kq << 2);
    const uint32_t smb = (uint32_t)__cvta_generic_to_shared(smf);
    const uint32_t sts = smb + (uint32_t)(r0 * LDPAD + (kq << 2)) * 4u;

    const int S = K >> 5;            // 32-K slabs

    // stage s -> buffer b = s&1 : A at b*STG_B, B at (2+b)*STG_B
    {
        // prologue: stage 0
        #pragma unroll
        for (int i = 0; i < 4; i++) {
            cp16(sts + 0 * STG_B + i * (32 * LDPAD * 4), Ag + (size_t)(i << 5) * K);
            cp16(sts + 2 * STG_B + i * (32 * LDPAD * 4), Bg + (size_t)(i << 5) * K);
        }
        CP_COMMIT();
    }

    for (int s = 0; s < S; s++) {
        if (s + 1 < S) {
            int kc = (s + 1) << 5;
            uint32_t b = (uint32_t)((s + 1) & 1) * STG_B;
            #pragma unroll
            for (int i = 0; i < 4; i++) {
                cp16(sts + b + i * (32 * LDPAD * 4),
                     Ag + (size_t)(i << 5) * K + kc);
                cp16(sts + b + 2 * STG_B + i * (32 * LDPAD * 4),
                     Bg + (size_t)(i << 5) * K + kc);
            }
            CP_COMMIT();
            CP_WAIT(1);
        } else {
            CP_WAIT(0);
        }
        __syncthreads();

        const float* As = smf + (s & 1) * STG_F;
        const float* Bs = smf + 2 * STG_F + (s & 1) * STG_F;
        #pragma unroll
        for (int kk = 0; kk < 4; kk++) {
            uint32_t a[4][4], b[4][2];
            #pragma unroll
            for (int m = 0; m < 4; m++) {
                const float* p = As + (wm * 64 + m * 16 + lr) * LDPAD + (kk << 3) + lc;
                a[m][0] = __float_as_uint(p[0]);
                a[m][1] = __float_as_uint(p[8 * LDPAD]);
                a[m][2] = __float_as_uint(p[4]);
                a[m][3] = __float_as_uint(p[8 * LDPAD + 4]);
            }
            #pragma unroll
            for (int n = 0; n < 4; n++) {
                const float* p = Bs + (wn * 32 + n * 8 + lr) * LDPAD + (kk << 3) + lc;
                b[n][0] = __float_as_uint(p[0]);
                b[n][1] = __float_as_uint(p[4]);
            }
            #pragma unroll
            for (int m = 0; m < 4; m++)
                #pragma unroll
                for (int n = 0; n < 4; n++)
                    asm volatile(
                        "mma.sync.aligned.m16n8k8.row.col.f32.tf32.tf32.f32 "
                        "{%0,%1,%2,%3}, {%4,%5,%6,%7}, {%8,%9}, {%0,%1,%2,%3};"
                        : "+f"(acc[m][n][0]), "+f"(acc[m][n][1]),
                          "+f"(acc[m][n][2]), "+f"(acc[m][n][3])
                        : "r"(a[m][0]), "r"(a[m][1]), "r"(a[m][2]), "r"(a[m][3]),
                          "r"(b[n][0]), "r"(b[n][1]));
        }
        __syncthreads();
    }

    // ---------------- epilogue ----------------
    const int rb = m0 + wm * 64;
    const int cb = n0 + wn * 32;
    #pragma unroll
    for (int m = 0; m < 4; m++) {
        #pragma unroll
        for (int n = 0; n < 4; n++) {
            int r  = rb + m * 16 + lr;
            int c  = cb + n * 8 + lc * 2;
            float2 bv = *reinterpret_cast<const float2*>(bias + c);
            #pragma unroll
            for (int half = 0; half < 2; half++) {
                int rr = r + half * 8;
                float o0 = acc[m][n][2 * half + 0] + bv.x;
                float o1 = acc[m][n][2 * half + 1] + bv.y;
                size_t off = (size_t)rr * N + c;
                if (MODE == 1) {
                    float2 rv = *reinterpret_cast<const float2*>(res + off);
                    o0 += rv.x; o1 += rv.y;
                }
                if (MODE == 2) {
                    o0 = 0.5f * o0 * (1.0f + erff(o0 * 0.70710678118654752f));
                    o1 = 0.5f * o1 * (1.0f + erff(o1 * 0.70710678118654752f));
                    o0 = tf32r(o0);     // fc1 feeds the FC2 GEMM: pre-round
                    o1 = tf32r(o1);
                }
                *reinterpret_cast<float2*>(C + off) = make_float2(o0, o1);
            }
        }
    }
}

// ---------------- LayerNorm: one block per row (tf32-rounded output) --------
__global__ __launch_bounds__(256) void ln_kernel(
    const float* __restrict__ x, const float* __restrict__ g,
    const float* __restrict__ b, float* __restrict__ out)
{
    int row = blockIdx.x;
    int t = threadIdx.x;
    const float4* xr = reinterpret_cast<const float4*>(x + (size_t)row * EMBED);
    float4 v = xr[t];
    float s  = v.x + v.y + v.z + v.w;
    float ss = v.x * v.x + v.y * v.y + v.z * v.z + v.w * v.w;
    #pragma unroll
    for (int o = 16; o > 0; o >>= 1) {
        s  += __shfl_xor_sync(0xffffffffu, s,  o);
        ss += __shfl_xor_sync(0xffffffffu, ss, o);
    }
    __shared__ float sm[8], sm2[8];
    int w = t >> 5, l = t & 31;
    if (l == 0) { sm[w] = s; sm2[w] = ss; }
    __syncthreads();
    float tot = 0.f, tot2 = 0.f;
    #pragma unroll
    for (int i = 0; i < 8; i++) { tot += sm[i]; tot2 += sm2[i]; }
    float mu   = tot * (1.0f / EMBED);
    float var  = tot2 * (1.0f / EMBED) - mu * mu;
    float rstd = rsqrtf(var + 1e-5f);
    float4 gg = reinterpret_cast<const float4*>(g)[t];
    float4 bb = reinterpret_cast<const float4*>(b)[t];
    float4 o;
    o.x = tf32r((v.x - mu) * rstd * gg.x + bb.x);
    o.y = tf32r((v.y - mu) * rstd * gg.y + bb.y);
    o.z = tf32r((v.z - mu) * rstd * gg.z + bb.z);
    o.w = tf32r((v.w - mu) * rstd * gg.w + bb.w);
    reinterpret_cast<float4*>(out + (size_t)row * EMBED)[t] = o;
}

// ---------------- Flash attention (fp32, online softmax, tf32 output) -------
__global__ __launch_bounds__(256) void flash_kernel(
    const float* __restrict__ qkv, float* __restrict__ out)
{
    const int KT = 32;
    __shared__ float Qs[64][65];
    __shared__ float Ks[KT][65];
    __shared__ float Vs[KT][65];
    __shared__ float Ps[64][33];

    int b = blockIdx.x >> 4;
    int h = blockIdx.x & 15;
    int q0 = blockIdx.y * 64;
    int t = threadIdx.x;
    int rg = t >> 3;     // 0..31
    int q8 = t & 7;      // 0..7

    const float* base = qkv + (size_t)b * SEQ * (3 * EMBED) + h * HD;

    for (int i = t; i < 64 * 64; i += 256) {
        int rr = i >> 6, dd = i & 63;
        Qs[rr][dd] = base[(size_t)(q0 + rr) * (3 * EMBED) + dd] * 0.125f;
    }

    float m0v = -1e30f, m1v = -1e30f, l0v = 0.f, l1v = 0.f;
    float acc0[8], acc1[8];
    #pragma unroll
    for (int i = 0; i < 8; i++) { acc0[i] = 0.f; acc1[i] = 0.f; }
    __syncthreads();

    for (int kt = 0; kt < SEQ; kt += KT) {
        for (int i = t; i < KT * 64; i += 256) {
            int rr = i >> 6, dd = i & 63;
            const float* kb = base + (size_t)(kt + rr) * (3 * EMBED) + dd;
            Ks[rr][dd] = kb[EMBED];
            Vs[rr][dd] = kb[2 * EMBED];
        }
        __syncthreads();

        float s0[4] = {0.f, 0.f, 0.f, 0.f};
        float s1[4] = {0.f, 0.f, 0.f, 0.f};
        #pragma unroll
        for (int d = 0; d < 64; d++) {
            float qa = Qs[rg][d];
            float qb = Qs[rg + 32][d];
            #pragma unroll
            for (int jj = 0; jj < 4; jj++) {
                float kv = Ks[q8 + 8 * jj][d];
                s0[jj] += qa * kv;
                s1[jj] += qb * kv;
            }
        }
        float mn0 = fmaxf(fmaxf(s0[0], s0[1]), fmaxf(s0[2], s0[3]));
        float mn1 = fmaxf(fmaxf(s1[0], s1[1]), fmaxf(s1[2], s1[3]));
        #pragma unroll
        for (int o = 1; o < 8; o <<= 1) {
            mn0 = fmaxf(mn0, __shfl_xor_sync(0xffffffffu, mn0, o));
            mn1 = fmaxf(mn1, __shfl_xor_sync(0xffffffffu, mn1, o));
        }
        mn0 = fmaxf(m0v, mn0);
        mn1 = fmaxf(m1v, mn1);
        float c0 = __expf(m0v - mn0);
        float c1 = __expf(m1v - mn1);
        float ls0 = 0.f, ls1 = 0.f;
        #pragma unroll
        for (int jj = 0; jj < 4; jj++) {
            float p0 = __expf(s0[jj] - mn0);
            float p1 = __expf(s1[jj] - mn1);
            Ps[rg][q8 + 8 * jj] = p0;
            Ps[rg + 32][q8 + 8 * jj] = p1;
            ls0 += p0;
            ls1 += p1;
        }
        #pragma unroll
        for (int o = 1; o < 8; o <<= 1) {
            ls0 += __shfl_xor_sync(0xffffffffu, ls0, o);
            ls1 += __shfl_xor_sync(0xffffffffu, ls1, o);
        }
        l0v = l0v * c0 + ls0;
        l1v = l1v * c1 + ls1;
        m0v = mn0;
        m1v = mn1;
        #pragma unroll
        for (int i = 0; i < 8; i++) { acc0[i] *= c0; acc1[i] *= c1; }
        __syncwarp();

        #pragma unroll
        for (int j = 0; j < KT; j++) {
            float pa = Ps[rg][j];
            float pb = Ps[rg + 32][j];
            #pragma unroll
            for (int dd = 0; dd < 8; dd++) {
                float v = Vs[j][q8 + 8 * dd];
                acc0[dd] += pa * v;
                acc1[dd] += pb * v;
            }
        }
        __syncthreads();
    }

    float inv0 = 1.f / l0v;
    float inv1 = 1.f / l1v;
    float* o0 = out + (size_t)(b * SEQ + q0 + rg) * EMBED + h * HD;
    float* o1 = o0 + (size_t)32 * EMBED;
    #pragma unroll
    for (int dd = 0; dd < 8; dd++) {
        o0[q8 + 8 * dd] = tf32r(acc0[dd] * inv0);
        o1[q8 + 8 * dd] = tf32r(acc1[dd] * inv1);
    }
}

// ---------------- launcher ---------------------------------------------------
extern "C" void kernel_launch(void* const* d_in, const int* in_sizes, int n_in,
                              void* d_out, int out_size)
{
    const float* x      = (const float*)d_in[0];
    const float* ln1_g  = (const float*)d_in[1];
    const float* ln1_b  = (const float*)d_in[2];
    const float* w_qkv  = (const float*)d_in[3];
    const float* b_qkv  = (const float*)d_in[4];
    const float* w_proj = (const float*)d_in[5];
    const float* b_proj = (const float*)d_in[6];
    const float* ln2_g  = (const float*)d_in[7];
    const float* ln2_b  = (const float*)d_in[8];
    const float* w_fc1  = (const float*)d_in[9];
    const float* b_fc1  = (const float*)d_in[10];
    const float* w_fc2  = (const float*)d_in[11];
    const float* b_fc2  = (const float*)d_in[12];
    float* out = (float*)d_out;

    float *h, *qkv, *attn, *fc1, *wt;
    cudaGetSymbolAddress((void**)&h,    g_h);
    cudaGetSymbolAddress((void**)&qkv,  g_qkv);
    cudaGetSymbolAddress((void**)&attn, g_attn);
    cudaGetSymbolAddress((void**)&fc1,  g_fc1);
    cudaGetSymbolAddress((void**)&wt,   g_wt);

    cudaFuncSetAttribute(tgemm<0>, cudaFuncAttributeMaxDynamicSharedMemorySize, TGEMM_SMEM);
    cudaFuncSetAttribute(tgemm<1>, cudaFuncAttributeMaxDynamicSharedMemorySize, TGEMM_SMEM);
    cudaFuncSetAttribute(tgemm<2>, cudaFuncAttributeMaxDynamicSharedMemorySize, TGEMM_SMEM);

    float* qkvT  = wt + WT_QKV;
    float* projT = wt + WT_PROJ;
    float* fc1T  = wt + WT_FC1;
    float* fc2T  = wt + WT_FC2;

    // 0) transpose weights to [N, K] (tf32-rounded, K-major)
    transpose_kernel<<<dim3(3 * EMBED / 32, EMBED / 32),   dim3(32, 8)>>>(w_qkv,  qkvT,  EMBED,   3 * EMBED);
    transpose_kernel<<<dim3(EMBED / 32,     EMBED / 32),   dim3(32, 8)>>>(w_proj, projT, EMBED,   EMBED);
    transpose_kernel<<<dim3(MLP_DIM / 32,   EMBED / 32),   dim3(32, 8)>>>(w_fc1,  fc1T,  EMBED,   MLP_DIM);
    transpose_kernel<<<dim3(EMBED / 32,     MLP_DIM / 32), dim3(32, 8)>>>(w_fc2,  fc2T,  MLP_DIM, EMBED);

    // 1) LN1: x -> h (tf32)
    ln_kernel<<<ROWS, 256>>>(x, ln1_g, ln1_b, h);

    // 2) QKV GEMM: h @ w_qkv + b_qkv -> qkv (fp32)
    tgemm<0><<<dim3(3 * EMBED / 128, ROWS / 128), 256, TGEMM_SMEM>>>(
        h, qkvT, b_qkv, nullptr, qkv, 3 * EMBED, EMBED);

    // 3) attention -> attn (tf32)
    flash_kernel<<<dim3(BATCH * HEADS, SEQ / 64), 256>>>(qkv, attn);

    // 4) proj + residual(x) -> out (fp32)
    tgemm<1><<<dim3(EMBED / 128, ROWS / 128), 256, TGEMM_SMEM>>>(
        attn, projT, b_proj, x, out, EMBED, EMBED);

    // 5) LN2: out -> h (tf32)
    ln_kernel<<<ROWS, 256>>>(out, ln2_g, ln2_b, h);

    // 6) FC1 + GELU: h @ w_fc1 -> fc1 (tf32)
    tgemm<2><<<dim3(MLP_DIM / 128, ROWS / 128), 256, TGEMM_SMEM>>>(
        h, fc1T, b_fc1, nullptr, fc1, MLP_DIM, EMBED);

    // 7) FC2 + residual(out) -> out (fp32, in-place elementwise safe)
    tgemm<1><<<dim3(EMBED / 128, ROWS / 128), 256, TGEMM_SMEM>>>(
        fc1, fc2T, b_fc2, out, out, EMBED, MLP_DIM);
}

// round 9
// speedup vs baseline: 2.7935x; 2.0142x over previous
#include <cuda_runtime.h>
#include <cuda_fp16.h>
#include <math.h>
#include <stdint.h>

#define EMBED 1024
#define HEADS 16
#define HD 64
#define MLP_DIM 4096
#define BATCH 8
#define SEQ 1024
#define ROWS (BATCH * SEQ)   // 8192

// ---------------- scratch (device globals: no allocation allowed) -----------
__device__ __half g_h[ROWS * EMBED];          // 16 MB (LN outputs, fp16)
__device__ float  g_qkv[ROWS * 3 * EMBED];    // 100 MB (fp32)
__device__ __half g_attn[ROWS * EMBED];       // 16 MB (fp16)
__device__ __half g_fc1[ROWS * MLP_DIM];      // 64 MB (fp16)
__device__ __half g_wt[12582912];             // 24 MB (transposed weights, fp16)

#define WT_QKV  0
#define WT_PROJ (3 * EMBED * EMBED)
#define WT_FC1  (WT_PROJ + EMBED * EMBED)
#define WT_FC2  (WT_FC1 + EMBED * MLP_DIM)

__device__ __forceinline__ void cp16(uint32_t dst, const void* src) {
    asm volatile("cp.async.cg.shared.global [%0], [%1], 16;"
                 :: "r"(dst), "l"(src) : "memory");
}
#define CP_COMMIT() asm volatile("cp.async.commit_group;" ::: "memory")
#define CP_WAIT(n)  asm volatile("cp.async.wait_group %0;" :: "n"(n) : "memory")

#define LDSM4(r0, r1, r2, r3, addr) \
    asm volatile("ldmatrix.sync.aligned.m8n8.x4.shared.b16 {%0,%1,%2,%3}, [%4];" \
                 : "=r"(r0), "=r"(r1), "=r"(r2), "=r"(r3) : "r"(addr))

// ---------------- weight transpose: out[N,K] = fp16(in[K,N]^T) --------------
__global__ __launch_bounds__(256) void transpose_kernel(
    const float* __restrict__ in, __half* __restrict__ out, int K, int N)
{
    __shared__ float tile[32][33];
    int n0 = blockIdx.x * 32, k0 = blockIdx.y * 32;
    int tx = threadIdx.x, ty = threadIdx.y;   // 32 x 8
    #pragma unroll
    for (int i = 0; i < 32; i += 8)
        tile[ty + i][tx] = in[(size_t)(k0 + ty + i) * N + n0 + tx];
    __syncthreads();
    #pragma unroll
    for (int i = 0; i < 32; i += 8)
        out[(size_t)(n0 + ty + i) * K + k0 + tx] = __float2half_rn(tile[tx][ty + i]);
}

// ---------------- fp16 mma.sync GEMM: C = A[M,K] @ WT[N,K]^T ----------------
// CTA 128x128, BK=32 (2 x k16), 8 warps (2M x 4N), warp tile 64x32, m16n8k16.
// A,WT fp16 (pre-rounded by producers). Acc fp32. 3-stage cp.async pipeline.
// MODE 0: +bias -> f32 | MODE 1: +bias+res -> f32 | MODE 2: +bias,GELU -> f16
#define ROWH   40                       // padded halves per smem row (80 B)
#define TILE_B (128 * ROWH * 2)         // 10240 bytes per operand tile
#define NSTAGE 3
#define TGEMM_SMEM (NSTAGE * 2 * TILE_B)   // 61440 bytes

template <int MODE>
__global__ __launch_bounds__(256, 2) void tgemm(
    const __half* __restrict__ A, const __half* __restrict__ WT,
    const float* __restrict__ bias, const float* __restrict__ res,
    void* __restrict__ Cv, int N, int K)
{
    extern __shared__ char smc[];
    const uint32_t smb = (uint32_t)__cvta_generic_to_shared(smc);
    const int t = threadIdx.x;
    const int warp = t >> 5, lane = t & 31;
    const int lr = lane >> 2, lc = lane & 3;
    const int wm = warp >> 2, wn = warp & 3;     // 2 x 4
    const int m0 = blockIdx.y << 7;
    const int n0 = blockIdx.x << 7;

    float acc[4][4][4];
    #pragma unroll
    for (int m = 0; m < 4; m++)
        #pragma unroll
        for (int n = 0; n < 4; n++)
            #pragma unroll
            for (int r = 0; r < 4; r++) acc[m][n][r] = 0.f;

    const __half* Ab = A  + (size_t)m0 * K;
    const __half* Bb = WT + (size_t)n0 * K;
    const int S = K >> 5;

    // loader: 512 16B-chunks per tile; thread t does chunks t, t+256 for A and B
    const int lrow0 = t >> 2,          lpart0 = t & 3;
    const int lrow1 = (t + 256) >> 2,  lpart1 = t & 3;   // (t+256)&3 == t&3

    // fragment addresses (constant parts)
    const int rA  = lane & 15;
    const int khA = (lane >> 4) << 3;
    const int rB  = (lane & 7) + ((lane >> 4) << 3);
    const int khB = ((lane >> 3) & 1) << 3;

    #define STAGE_LOAD(buf, kc)                                                  \
        do {                                                                     \
            uint32_t sa = smb + (uint32_t)(buf) * (2 * TILE_B);                  \
            uint32_t sb = sa + TILE_B;                                           \
            cp16(sa + lrow0 * 80 + lpart0 * 16,                                  \
                 Ab + (size_t)lrow0 * K + (kc) + lpart0 * 8);                    \
            cp16(sa + lrow1 * 80 + lpart1 * 16,                                  \
                 Ab + (size_t)lrow1 * K + (kc) + lpart1 * 8);                    \
            cp16(sb + lrow0 * 80 + lpart0 * 16,                                  \
                 Bb + (size_t)lrow0 * K + (kc) + lpart0 * 8);                    \
            cp16(sb + lrow1 * 80 + lpart1 * 16,                                  \
                 Bb + (size_t)lrow1 * K + (kc) + lpart1 * 8);                    \
        } while (0)

    STAGE_LOAD(0, 0);
    CP_COMMIT();
    if (S > 1) { STAGE_LOAD(1, 32); CP_COMMIT(); }

    int buf = 0;
    for (int s = 0; s < S; s++) {
        if (s + 2 < S) { CP_WAIT(1); } else { CP_WAIT(0); }
        __syncthreads();

        const uint32_t As = smb + (uint32_t)buf * (2 * TILE_B);
        const uint32_t Bs = As + TILE_B;
        #pragma unroll
        for (int kk = 0; kk < 2; kk++) {
            uint32_t a[4][4], b[4][2];
            #pragma unroll
            for (int m = 0; m < 4; m++) {
                uint32_t addr = As + (uint32_t)(wm * 64 + m * 16 + rA) * 80u
                              + (uint32_t)(kk * 16 + khA) * 2u;
                LDSM4(a[m][0], a[m][1], a[m][2], a[m][3], addr);
            }
            #pragma unroll
            for (int np = 0; np < 2; np++) {
                uint32_t addr = Bs + (uint32_t)(wn * 32 + np * 16 + rB) * 80u
                              + (uint32_t)(kk * 16 + khB) * 2u;
                LDSM4(b[2 * np][0], b[2 * np][1], b[2 * np + 1][0], b[2 * np + 1][1], addr);
            }
            #pragma unroll
            for (int m = 0; m < 4; m++)
                #pragma unroll
                for (int n = 0; n < 4; n++)
                    asm volatile(
                        "mma.sync.aligned.m16n8k16.row.col.f32.f16.f16.f32 "
                        "{%0,%1,%2,%3}, {%4,%5,%6,%7}, {%8,%9}, {%0,%1,%2,%3};"
                        : "+f"(acc[m][n][0]), "+f"(acc[m][n][1]),
                          "+f"(acc[m][n][2]), "+f"(acc[m][n][3])
                        : "r"(a[m][0]), "r"(a[m][1]), "r"(a[m][2]), "r"(a[m][3]),
                          "r"(b[n][0]), "r"(b[n][1]));
        }
        __syncthreads();

        if (s + 2 < S) {
            int nb = buf + 2; if (nb >= NSTAGE) nb -= NSTAGE;
            STAGE_LOAD(nb, (s + 2) << 5);
            CP_COMMIT();
        }
        buf = buf + 1; if (buf == NSTAGE) buf = 0;
    }
    #undef STAGE_LOAD

    // ---------------- epilogue ----------------
    const int rb = m0 + wm * 64;
    const int cb = n0 + wn * 32;
    #pragma unroll
    for (int m = 0; m < 4; m++) {
        #pragma unroll
        for (int n = 0; n < 4; n++) {
            int r = rb + m * 16 + lr;
            int c = cb + n * 8 + lc * 2;
            float2 bv = *reinterpret_cast<const float2*>(bias + c);
            #pragma unroll
            for (int half_ = 0; half_ < 2; half_++) {
                int rr = r + half_ * 8;
                float o0 = acc[m][n][2 * half_ + 0] + bv.x;
                float o1 = acc[m][n][2 * half_ + 1] + bv.y;
                size_t off = (size_t)rr * N + c;
                if (MODE == 1) {
                    float2 rv = *reinterpret_cast<const float2*>(res + off);
                    o0 += rv.x; o1 += rv.y;
                }
                if (MODE == 2) {
                    o0 = 0.5f * o0 * (1.0f + erff(o0 * 0.70710678118654752f));
                    o1 = 0.5f * o1 * (1.0f + erff(o1 * 0.70710678118654752f));
                    *reinterpret_cast<__half2*>((__half*)Cv + off) =
                        __floats2half2_rn(o0, o1);
                } else {
                    *reinterpret_cast<float2*>((float*)Cv + off) = make_float2(o0, o1);
                }
            }
        }
    }
}

// ---------------- LayerNorm: one block per row (fp16 output) ----------------
__global__ __launch_bounds__(256) void ln_kernel(
    const float* __restrict__ x, const float* __restrict__ g,
    const float* __restrict__ b, __half* __restrict__ out)
{
    int row = blockIdx.x;
    int t = threadIdx.x;
    const float4* xr = reinterpret_cast<const float4*>(x + (size_t)row * EMBED);
    float4 v = xr[t];
    float s  = v.x + v.y + v.z + v.w;
    float ss = v.x * v.x + v.y * v.y + v.z * v.z + v.w * v.w;
    #pragma unroll
    for (int o = 16; o > 0; o >>= 1) {
        s  += __shfl_xor_sync(0xffffffffu, s,  o);
        ss += __shfl_xor_sync(0xffffffffu, ss, o);
    }
    __shared__ float sm[8], sm2[8];
    int w = t >> 5, l = t & 31;
    if (l == 0) { sm[w] = s; sm2[w] = ss; }
    __syncthreads();
    float tot = 0.f, tot2 = 0.f;
    #pragma unroll
    for (int i = 0; i < 8; i++) { tot += sm[i]; tot2 += sm2[i]; }
    float mu   = tot * (1.0f / EMBED);
    float var  = tot2 * (1.0f / EMBED) - mu * mu;
    float rstd = rsqrtf(var + 1e-5f);
    float4 gg = reinterpret_cast<const float4*>(g)[t];
    float4 bb = reinterpret_cast<const float4*>(b)[t];
    __half2* op = reinterpret_cast<__half2*>(out + (size_t)row * EMBED);
    op[2 * t + 0] = __floats2half2_rn((v.x - mu) * rstd * gg.x + bb.x,
                                      (v.y - mu) * rstd * gg.y + bb.y);
    op[2 * t + 1] = __floats2half2_rn((v.z - mu) * rstd * gg.z + bb.z,
                                      (v.w - mu) * rstd * gg.w + bb.w);
}

// ---------------- Flash attention (fp32 math, fp16 output) ------------------
__global__ __launch_bounds__(256) void flash_kernel(
    const float* __restrict__ qkv, __half* __restrict__ out)
{
    const int KT = 32;
    __shared__ float Qs[64][65];
    __shared__ float Ks[KT][65];
    __shared__ float Vs[KT][65];
    __shared__ float Ps[64][33];

    int b = blockIdx.x >> 4;
    int h = blockIdx.x & 15;
    int q0 = blockIdx.y * 64;
    int t = threadIdx.x;
    int rg = t >> 3;     // 0..31
    int q8 = t & 7;      // 0..7

    const float* base = qkv + (size_t)b * SEQ * (3 * EMBED) + h * HD;

    for (int i = t; i < 64 * 64; i += 256) {
        int rr = i >> 6, dd = i & 63;
        Qs[rr][dd] = base[(size_t)(q0 + rr) * (3 * EMBED) + dd] * 0.125f;
    }

    float m0v = -1e30f, m1v = -1e30f, l0v = 0.f, l1v = 0.f;
    float acc0[8], acc1[8];
    #pragma unroll
    for (int i = 0; i < 8; i++) { acc0[i] = 0.f; acc1[i] = 0.f; }
    __syncthreads();

    for (int kt = 0; kt < SEQ; kt += KT) {
        for (int i = t; i < KT * 64; i += 256) {
            int rr = i >> 6, dd = i & 63;
            const float* kb = base + (size_t)(kt + rr) * (3 * EMBED) + dd;
            Ks[rr][dd] = kb[EMBED];
            Vs[rr][dd] = kb[2 * EMBED];
        }
        __syncthreads();

        float s0[4] = {0.f, 0.f, 0.f, 0.f};
        float s1[4] = {0.f, 0.f, 0.f, 0.f};
        #pragma unroll
        for (int d = 0; d < 64; d++) {
            float qa = Qs[rg][d];
            float qb = Qs[rg + 32][d];
            #pragma unroll
            for (int jj = 0; jj < 4; jj++) {
                float kv = Ks[q8 + 8 * jj][d];
                s0[jj] += qa * kv;
                s1[jj] += qb * kv;
            }
        }
        float mn0 = fmaxf(fmaxf(s0[0], s0[1]), fmaxf(s0[2], s0[3]));
        float mn1 = fmaxf(fmaxf(s1[0], s1[1]), fmaxf(s1[2], s1[3]));
        #pragma unroll
        for (int o = 1; o < 8; o <<= 1) {
            mn0 = fmaxf(mn0, __shfl_xor_sync(0xffffffffu, mn0, o));
            mn1 = fmaxf(mn1, __shfl_xor_sync(0xffffffffu, mn1, o));
        }
        mn0 = fmaxf(m0v, mn0);
        mn1 = fmaxf(m1v, mn1);
        float c0 = __expf(m0v - mn0);
        float c1 = __expf(m1v - mn1);
        float ls0 = 0.f, ls1 = 0.f;
        #pragma unroll
        for (int jj = 0; jj < 4; jj++) {
            float p0 = __expf(s0[jj] - mn0);
            float p1 = __expf(s1[jj] - mn1);
            Ps[rg][q8 + 8 * jj] = p0;
            Ps[rg + 32][q8 + 8 * jj] = p1;
            ls0 += p0;
            ls1 += p1;
        }
        #pragma unroll
        for (int o = 1; o < 8; o <<= 1) {
            ls0 += __shfl_xor_sync(0xffffffffu, ls0, o);
            ls1 += __shfl_xor_sync(0xffffffffu, ls1, o);
        }
        l0v = l0v * c0 + ls0;
        l1v = l1v * c1 + ls1;
        m0v = mn0;
        m1v = mn1;
        #pragma unroll
        for (int i = 0; i < 8; i++) { acc0[i] *= c0; acc1[i] *= c1; }
        __syncwarp();

        #pragma unroll
        for (int j = 0; j < KT; j++) {
            float pa = Ps[rg][j];
            float pb = Ps[rg + 32][j];
            #pragma unroll
            for (int dd = 0; dd < 8; dd++) {
                float v = Vs[j][q8 + 8 * dd];
                acc0[dd] += pa * v;
                acc1[dd] += pb * v;
            }
        }
        __syncthreads();
    }

    float inv0 = 1.f / l0v;
    float inv1 = 1.f / l1v;
    __half* o0 = out + (size_t)(b * SEQ + q0 + rg) * EMBED + h * HD;
    __half* o1 = o0 + (size_t)32 * EMBED;
    #pragma unroll
    for (int dd = 0; dd < 8; dd++) {
        o0[q8 + 8 * dd] = __float2half_rn(acc0[dd] * inv0);
        o1[q8 + 8 * dd] = __float2half_rn(acc1[dd] * inv1);
    }
}

// ---------------- launcher ---------------------------------------------------
extern "C" void kernel_launch(void* const* d_in, const int* in_sizes, int n_in,
                              void* d_out, int out_size)
{
    const float* x      = (const float*)d_in[0];
    const float* ln1_g  = (const float*)d_in[1];
    const float* ln1_b  = (const float*)d_in[2];
    const float* w_qkv  = (const float*)d_in[3];
    const float* b_qkv  = (const float*)d_in[4];
    const float* w_proj = (const float*)d_in[5];
    const float* b_proj = (const float*)d_in[6];
    const float* ln2_g  = (const float*)d_in[7];
    const float* ln2_b  = (const float*)d_in[8];
    const float* w_fc1  = (const float*)d_in[9];
    const float* b_fc1  = (const float*)d_in[10];
    const float* w_fc2  = (const float*)d_in[11];
    const float* b_fc2  = (const float*)d_in[12];
    float* out = (float*)d_out;

    __half *h, *attn, *fc1, *wt;
    float *qkv;
    cudaGetSymbolAddress((void**)&h,    g_h);
    cudaGetSymbolAddress((void**)&qkv,  g_qkv);
    cudaGetSymbolAddress((void**)&attn, g_attn);
    cudaGetSymbolAddress((void**)&fc1,  g_fc1);
    cudaGetSymbolAddress((void**)&wt,   g_wt);

    cudaFuncSetAttribute(tgemm<0>, cudaFuncAttributeMaxDynamicSharedMemorySize, TGEMM_SMEM);
    cudaFuncSetAttribute(tgemm<1>, cudaFuncAttributeMaxDynamicSharedMemorySize, TGEMM_SMEM);
    cudaFuncSetAttribute(tgemm<2>, cudaFuncAttributeMaxDynamicSharedMemorySize, TGEMM_SMEM);

    __half* qkvT  = wt + WT_QKV;
    __half* projT = wt + WT_PROJ;
    __half* fc1T  = wt + WT_FC1;
    __half* fc2T  = wt + WT_FC2;

    // 0) transpose weights to [N, K] fp16 (K-major)
    transpose_kernel<<<dim3(3 * EMBED / 32, EMBED / 32),   dim3(32, 8)>>>(w_qkv,  qkvT,  EMBED,   3 * EMBED);
    transpose_kernel<<<dim3(EMBED / 32,     EMBED / 32),   dim3(32, 8)>>>(w_proj, projT, EMBED,   EMBED);
    transpose_kernel<<<dim3(MLP_DIM / 32,   EMBED / 32),   dim3(32, 8)>>>(w_fc1,  fc1T,  EMBED,   MLP_DIM);
    transpose_kernel<<<dim3(EMBED / 32,     MLP_DIM / 32), dim3(32, 8)>>>(w_fc2,  fc2T,  MLP_DIM, EMBED);

    // 1) LN1: x -> h (fp16)
    ln_kernel<<<ROWS, 256>>>(x, ln1_g, ln1_b, h);

    // 2) QKV GEMM: h @ w_qkv + b_qkv -> qkv (fp32)
    tgemm<0><<<dim3(3 * EMBED / 128, ROWS / 128), 256, TGEMM_SMEM>>>(
        h, qkvT, b_qkv, nullptr, qkv, 3 * EMBED, EMBED);

    // 3) attention -> attn (fp16)
    flash_kernel<<<dim3(BATCH * HEADS, SEQ / 64), 256>>>(qkv, attn);

    // 4) proj + residual(x) -> out (fp32)
    tgemm<1><<<dim3(EMBED / 128, ROWS / 128), 256, TGEMM_SMEM>>>(
        attn, projT, b_proj, x, out, EMBED, EMBED);

    // 5) LN2: out -> h (fp16)
    ln_kernel<<<ROWS, 256>>>(out, ln2_g, ln2_b, h);

    // 6) FC1 + GELU: h @ w_fc1 -> fc1 (fp16)
    tgemm<2><<<dim3(MLP_DIM / 128, ROWS / 128), 256, TGEMM_SMEM>>>(
        h, fc1T, b_fc1, nullptr, fc1, MLP_DIM, EMBED);

    // 7) FC2 + residual(out) -> out (fp32, in-place elementwise safe)
    tgemm<1><<<dim3(EMBED / 128, ROWS / 128), 256, TGEMM_SMEM>>>(
        fc1, fc2T, b_fc2, out, out, EMBED, MLP_DIM);
}

// round 11
// speedup vs baseline: 6.6961x; 2.3970x over previous
#include <cuda_runtime.h>
#include <cuda_fp16.h>
#include <math.h>
#include <stdint.h>

#define EMBED 1024
#define HEADS 16
#define HD 64
#define MLP_DIM 4096
#define BATCH 8
#define SEQ 1024
#define ROWS (BATCH * SEQ)   // 8192

// ---------------- scratch (device globals: no allocation allowed) -----------
__device__ __half g_h[ROWS * EMBED];          // 16 MB (LN outputs, fp16)
__device__ __half g_qkv[ROWS * 3 * EMBED];    // 50 MB (fp16)
__device__ __half g_attn[ROWS * EMBED];       // 16 MB (fp16)
__device__ __half g_fc1[ROWS * MLP_DIM];      // 64 MB (fp16)
__device__ __half g_wt[12582912];             // 24 MB (transposed weights, fp16)

#define WT_QKV  0
#define WT_PROJ (3 * EMBED * EMBED)
#define WT_FC1  (WT_PROJ + EMBED * EMBED)
#define WT_FC2  (WT_FC1 + EMBED * MLP_DIM)

__device__ __forceinline__ void cp16(uint32_t dst, const void* src) {
    asm volatile("cp.async.cg.shared.global [%0], [%1], 16;"
                 :: "r"(dst), "l"(src) : "memory");
}
#define CP_COMMIT() asm volatile("cp.async.commit_group;" ::: "memory")
#define CP_WAIT(n)  asm volatile("cp.async.wait_group %0;" :: "n"(n) : "memory")

#define LDSM4(r0, r1, r2, r3, addr) \
    asm volatile("ldmatrix.sync.aligned.m8n8.x4.shared.b16 {%0,%1,%2,%3}, [%4];" \
                 : "=r"(r0), "=r"(r1), "=r"(r2), "=r"(r3) : "r"(addr))
#define LDSM4T(r0, r1, r2, r3, addr) \
    asm volatile("ldmatrix.sync.aligned.m8n8.x4.trans.shared.b16 {%0,%1,%2,%3}, [%4];" \
                 : "=r"(r0), "=r"(r1), "=r"(r2), "=r"(r3) : "r"(addr))

#define HMMA(d, a0, a1, a2, a3, b0, b1) \
    asm volatile("mma.sync.aligned.m16n8k16.row.col.f32.f16.f16.f32 " \
                 "{%0,%1,%2,%3}, {%4,%5,%6,%7}, {%8,%9}, {%0,%1,%2,%3};" \
                 : "+f"((d)[0]), "+f"((d)[1]), "+f"((d)[2]), "+f"((d)[3]) \
                 : "r"(a0), "r"(a1), "r"(a2), "r"(a3), "r"(b0), "r"(b1))

__device__ __forceinline__ uint32_t pack2(float x, float y) {
    __half2 h = __floats2half2_rn(x, y);
    return *reinterpret_cast<uint32_t*>(&h);
}

// ---------------- weight transpose: out[N,K] = fp16(in[K,N]^T) --------------
__global__ __launch_bounds__(256) void transpose_kernel(
    const float* __restrict__ in, __half* __restrict__ out, int K, int N)
{
    __shared__ float tile[32][33];
    int n0 = blockIdx.x * 32, k0 = blockIdx.y * 32;
    int tx = threadIdx.x, ty = threadIdx.y;   // 32 x 8
    #pragma unroll
    for (int i = 0; i < 32; i += 8)
        tile[ty + i][tx] = in[(size_t)(k0 + ty + i) * N + n0 + tx];
    __syncthreads();
    #pragma unroll
    for (int i = 0; i < 32; i += 8)
        out[(size_t)(n0 + ty + i) * K + k0 + tx] = __float2half_rn(tile[tx][ty + i]);
}

// ---------------- fp16 mma.sync GEMM: C = A[M,K] @ WT[N,K]^T ----------------
// CTA 128x128, BK=32 (2 x k16), 8 warps (2M x 4N), warp tile 64x32, m16n8k16.
// MODE 0: +bias -> f32 | MODE 1: +bias+res -> f32 | MODE 2: +bias,GELU -> f16
// MODE 3: +bias -> f16
#define ROWH   40
#define TILE_B (128 * ROWH * 2)
#define NSTAGE 3
#define TGEMM_SMEM (NSTAGE * 2 * TILE_B)   // 61440 bytes

template <int MODE>
__global__ __launch_bounds__(256, 2) void tgemm(
    const __half* __restrict__ A, const __half* __restrict__ WT,
    const float* __restrict__ bias, const float* __restrict__ res,
    void* __restrict__ Cv, int N, int K)
{
    extern __shared__ char smc[];
    const uint32_t smb = (uint32_t)__cvta_generic_to_shared(smc);
    const int t = threadIdx.x;
    const int warp = t >> 5, lane = t & 31;
    const int lr = lane >> 2, lc = lane & 3;
    const int wm = warp >> 2, wn = warp & 3;
    const int m0 = blockIdx.y << 7;
    const int n0 = blockIdx.x << 7;

    float acc[4][4][4];
    #pragma unroll
    for (int m = 0; m < 4; m++)
        #pragma unroll
        for (int n = 0; n < 4; n++)
            #pragma unroll
            for (int r = 0; r < 4; r++) acc[m][n][r] = 0.f;

    const __half* Ab = A  + (size_t)m0 * K;
    const __half* Bb = WT + (size_t)n0 * K;
    const int S = K >> 5;

    const int lrow0 = t >> 2,          lpart0 = t & 3;
    const int lrow1 = (t + 256) >> 2,  lpart1 = t & 3;

    const int rA  = lane & 15;
    const int khA = (lane >> 4) << 3;
    const int rB  = (lane & 7) + ((lane >> 4) << 3);
    const int khB = ((lane >> 3) & 1) << 3;

    #define STAGE_LOAD(buf, kc)                                                  \
        do {                                                                     \
            uint32_t sa = smb + (uint32_t)(buf) * (2 * TILE_B);                  \
            uint32_t sb = sa + TILE_B;                                           \
            cp16(sa + lrow0 * 80 + lpart0 * 16,                                  \
                 Ab + (size_t)lrow0 * K + (kc) + lpart0 * 8);                    \
            cp16(sa + lrow1 * 80 + lpart1 * 16,                                  \
                 Ab + (size_t)lrow1 * K + (kc) + lpart1 * 8);                    \
            cp16(sb + lrow0 * 80 + lpart0 * 16,                                  \
                 Bb + (size_t)lrow0 * K + (kc) + lpart0 * 8);                    \
            cp16(sb + lrow1 * 80 + lpart1 * 16,                                  \
                 Bb + (size_t)lrow1 * K + (kc) + lpart1 * 8);                    \
        } while (0)

    STAGE_LOAD(0, 0);
    CP_COMMIT();
    if (S > 1) { STAGE_LOAD(1, 32); CP_COMMIT(); }

    int buf = 0;
    for (int s = 0; s < S; s++) {
        if (s + 2 < S) { CP_WAIT(1); } else { CP_WAIT(0); }
        __syncthreads();

        const uint32_t As = smb + (uint32_t)buf * (2 * TILE_B);
        const uint32_t Bs = As + TILE_B;
        #pragma unroll
        for (int kk = 0; kk < 2; kk++) {
            uint32_t a[4][4], b[4][2];
            #pragma unroll
            for (int m = 0; m < 4; m++) {
                uint32_t addr = As + (uint32_t)(wm * 64 + m * 16 + rA) * 80u
                              + (uint32_t)(kk * 16 + khA) * 2u;
                LDSM4(a[m][0], a[m][1], a[m][2], a[m][3], addr);
            }
            #pragma unroll
            for (int np = 0; np < 2; np++) {
                uint32_t addr = Bs + (uint32_t)(wn * 32 + np * 16 + rB) * 80u
                              + (uint32_t)(kk * 16 + khB) * 2u;
                LDSM4(b[2 * np][0], b[2 * np][1], b[2 * np + 1][0], b[2 * np + 1][1], addr);
            }
            #pragma unroll
            for (int m = 0; m < 4; m++)
                #pragma unroll
                for (int n = 0; n < 4; n++)
                    HMMA(acc[m][n], a[m][0], a[m][1], a[m][2], a[m][3],
                         b[n][0], b[n][1]);
        }
        __syncthreads();

        if (s + 2 < S) {
            int nb = buf + 2; if (nb >= NSTAGE) nb -= NSTAGE;
            STAGE_LOAD(nb, (s + 2) << 5);
            CP_COMMIT();
        }
        buf = buf + 1; if (buf == NSTAGE) buf = 0;
    }
    #undef STAGE_LOAD

    // ---------------- epilogue ----------------
    const int rb = m0 + wm * 64;
    const int cb = n0 + wn * 32;
    #pragma unroll
    for (int m = 0; m < 4; m++) {
        #pragma unroll
        for (int n = 0; n < 4; n++) {
            int r = rb + m * 16 + lr;
            int c = cb + n * 8 + lc * 2;
            float2 bv = *reinterpret_cast<const float2*>(bias + c);
            #pragma unroll
            for (int half_ = 0; half_ < 2; half_++) {
                int rr = r + half_ * 8;
                float o0 = acc[m][n][2 * half_ + 0] + bv.x;
                float o1 = acc[m][n][2 * half_ + 1] + bv.y;
                size_t off = (size_t)rr * N + c;
                if (MODE == 1) {
                    float2 rv = *reinterpret_cast<const float2*>(res + off);
                    o0 += rv.x; o1 += rv.y;
                }
                if (MODE == 2) {
                    o0 = 0.5f * o0 * (1.0f + erff(o0 * 0.70710678118654752f));
                    o1 = 0.5f * o1 * (1.0f + erff(o1 * 0.70710678118654752f));
                }
                if (MODE == 2 || MODE == 3) {
                    *reinterpret_cast<__half2*>((__half*)Cv + off) =
                        __floats2half2_rn(o0, o1);
                } else {
                    *reinterpret_cast<float2*>((float*)Cv + off) = make_float2(o0, o1);
                }
            }
        }
    }
}

// ---------------- LayerNorm: one block per row (fp16 output) ----------------
__global__ __launch_bounds__(256) void ln_kernel(
    const float* __restrict__ x, const float* __restrict__ g,
    const float* __restrict__ b, __half* __restrict__ out)
{
    int row = blockIdx.x;
    int t = threadIdx.x;
    const float4* xr = reinterpret_cast<const float4*>(x + (size_t)row * EMBED);
    float4 v = xr[t];
    float s  = v.x + v.y + v.z + v.w;
    float ss = v.x * v.x + v.y * v.y + v.z * v.z + v.w * v.w;
    #pragma unroll
    for (int o = 16; o > 0; o >>= 1) {
        s  += __shfl_xor_sync(0xffffffffu, s,  o);
        ss += __shfl_xor_sync(0xffffffffu, ss, o);
    }
    __shared__ float sm[8], sm2[8];
    int w = t >> 5, l = t & 31;
    if (l == 0) { sm[w] = s; sm2[w] = ss; }
    __syncthreads();
    float tot = 0.f, tot2 = 0.f;
    #pragma unroll
    for (int i = 0; i < 8; i++) { tot += sm[i]; tot2 += sm2[i]; }
    float mu   = tot * (1.0f / EMBED);
    float var  = tot2 * (1.0f / EMBED) - mu * mu;
    float rstd = rsqrtf(var + 1e-5f);
    float4 gg = reinterpret_cast<const float4*>(g)[t];
    float4 bb = reinterpret_cast<const float4*>(b)[t];
    __half2* op = reinterpret_cast<__half2*>(out + (size_t)row * EMBED);
    op[2 * t + 0] = __floats2half2_rn((v.x - mu) * rstd * gg.x + bb.x,
                                      (v.y - mu) * rstd * gg.y + bb.y);
    op[2 * t + 1] = __floats2half2_rn((v.z - mu) * rstd * gg.z + bb.z,
                                      (v.w - mu) * rstd * gg.w + bb.w);
}

// ---------------- Flash attention, fp16 tensor cores (FA2 style) ------------
// grid (B*H, SEQ/64), 128 threads (4 warps x 16 Q rows). KV tiles of 64,
// double-buffered cp.async. Softmax in registers; P fragments taken directly
// from S accumulators; V via ldmatrix.trans.
#define FPITCH 72            // halves per smem row
#define FP_B   (FPITCH * 2)  // 144 bytes

__global__ __launch_bounds__(128) void flash_mma(
    const __half* __restrict__ qkv, __half* __restrict__ out)
{
    __shared__ __half Qs[64 * FPITCH];
    __shared__ __half Ks[2][64 * FPITCH];
    __shared__ __half Vs[2][64 * FPITCH];

    const int bh = blockIdx.x;
    const int b = bh >> 4, h = bh & 15;
    const int q0 = blockIdx.y << 6;
    const int t = threadIdx.x;
    const int warp = t >> 5, lane = t & 31;
    const int lr = lane >> 2, lc = lane & 3;

    const __half* base  = qkv + (size_t)b * SEQ * (3 * EMBED) + h * HD;
    const __half* kbase = base + EMBED;
    const __half* vbase = base + 2 * EMBED;

    const int r0 = t >> 3;   // 0..15
    const int cp = t & 7;    // 0..7

    const uint32_t qsm = (uint32_t)__cvta_generic_to_shared(Qs);
    const uint32_t ksm = (uint32_t)__cvta_generic_to_shared(Ks);
    const uint32_t vsm = (uint32_t)__cvta_generic_to_shared(Vs);

    // group 0: Q + K0 + V0
    #pragma unroll
    for (int i = 0; i < 4; i++) {
        int row = r0 + 16 * i;
        cp16(qsm + row * FP_B + cp * 16,
             base  + (size_t)(q0 + row) * (3 * EMBED) + cp * 8);
        cp16(ksm + row * FP_B + cp * 16,
             kbase + (size_t)row * (3 * EMBED) + cp * 8);
        cp16(vsm + row * FP_B + cp * 16,
             vbase + (size_t)row * (3 * EMBED) + cp * 8);
    }
    CP_COMMIT();
    // group 1: K1 + V1
    #pragma unroll
    for (int i = 0; i < 4; i++) {
        int row = r0 + 16 * i;
        cp16(ksm + 64 * FP_B + row * FP_B + cp * 16,
             kbase + (size_t)(64 + row) * (3 * EMBED) + cp * 8);
        cp16(vsm + 64 * FP_B + row * FP_B + cp * 16,
             vbase + (size_t)(64 + row) * (3 * EMBED) + cp * 8);
    }
    CP_COMMIT();

    float oacc[8][4];
    #pragma unroll
    for (int n = 0; n < 8; n++)
        #pragma unroll
        for (int c = 0; c < 4; c++) oacc[n][c] = 0.f;
    float m0v = -1e30f, m1v = -1e30f, l0v = 0.f, l1v = 0.f;

    const uint32_t qaddr0 = qsm + (uint32_t)(16 * warp + (lane & 15)) * FP_B
                          + (uint32_t)((lane >> 4) << 3) * 2u;
    const int rB  = (lane & 7) + ((lane >> 4) << 3);
    const int khB = ((lane >> 3) & 1) << 3;
    const uint32_t vrow = (uint32_t)(lane & 15);
    const uint32_t voff = (uint32_t)((lane >> 4) << 3) * 2u;

    for (int kt = 0; kt < 16; kt++) {
        if (kt < 15) { CP_WAIT(1); } else { CP_WAIT(0); }
        __syncthreads();
        const uint32_t kb = ksm + (uint32_t)(kt & 1) * (64 * FP_B);
        const uint32_t vb = vsm + (uint32_t)(kt & 1) * (64 * FP_B);

        // ---- S = Q @ K^T ----
        float sacc[8][4];
        #pragma unroll
        for (int n = 0; n < 8; n++)
            #pragma unroll
            for (int c = 0; c < 4; c++) sacc[n][c] = 0.f;

        #pragma unroll
        for (int kk = 0; kk < 4; kk++) {
            uint32_t a0, a1, a2, a3;
            LDSM4(a0, a1, a2, a3, qaddr0 + (uint32_t)kk * 32u);
            uint32_t bk[8][2];
            #pragma unroll
            for (int np = 0; np < 4; np++) {
                uint32_t addr = kb + (uint32_t)(16 * np + rB) * FP_B
                              + (uint32_t)(16 * kk + khB) * 2u;
                LDSM4(bk[2 * np][0], bk[2 * np][1],
                      bk[2 * np + 1][0], bk[2 * np + 1][1], addr);
            }
            #pragma unroll
            for (int n = 0; n < 8; n++)
                HMMA(sacc[n], a0, a1, a2, a3, bk[n][0], bk[n][1]);
        }

        // ---- online softmax (rows lr and lr+8; a row = 4 lanes via lc) ----
        #pragma unroll
        for (int n = 0; n < 8; n++)
            #pragma unroll
            for (int c = 0; c < 4; c++) sacc[n][c] *= 0.125f;

        float mx0 = -1e30f, mx1 = -1e30f;
        #pragma unroll
        for (int n = 0; n < 8; n++) {
            mx0 = fmaxf(mx0, fmaxf(sacc[n][0], sacc[n][1]));
            mx1 = fmaxf(mx1, fmaxf(sacc[n][2], sacc[n][3]));
        }
        mx0 = fmaxf(mx0, __shfl_xor_sync(0xffffffffu, mx0, 1));
        mx0 = fmaxf(mx0, __shfl_xor_sync(0xffffffffu, mx0, 2));
        mx1 = fmaxf(mx1, __shfl_xor_sync(0xffffffffu, mx1, 1));
        mx1 = fmaxf(mx1, __shfl_xor_sync(0xffffffffu, mx1, 2));

        float mn0 = fmaxf(m0v, mx0), mn1 = fmaxf(m1v, mx1);
        float c0 = __expf(m0v - mn0), c1 = __expf(m1v - mn1);

        uint32_t ph[8][2];
        float ls0 = 0.f, ls1 = 0.f;
        #pragma unroll
        for (int n = 0; n < 8; n++) {
            float p0 = __expf(sacc[n][0] - mn0);
            float p1 = __expf(sacc[n][1] - mn0);
            float p2 = __expf(sacc[n][2] - mn1);
            float p3 = __expf(sacc[n][3] - mn1);
            ls0 += p0 + p1;
            ls1 += p2 + p3;
            ph[n][0] = pack2(p0, p1);
            ph[n][1] = pack2(p2, p3);
        }
        ls0 += __shfl_xor_sync(0xffffffffu, ls0, 1);
        ls0 += __shfl_xor_sync(0xffffffffu, ls0, 2);
        ls1 += __shfl_xor_sync(0xffffffffu, ls1, 1);
        ls1 += __shfl_xor_sync(0xffffffffu, ls1, 2);

        l0v = l0v * c0 + ls0;
        l1v = l1v * c1 + ls1;
        m0v = mn0; m1v = mn1;
        #pragma unroll
        for (int n = 0; n < 8; n++) {
            oacc[n][0] *= c0; oacc[n][1] *= c0;
            oacc[n][2] *= c1; oacc[n][3] *= c1;
        }

        // ---- O += P @ V ----  (A frags straight from score accumulators)
        #pragma unroll
        for (int j = 0; j < 4; j++) {
            uint32_t pa0 = ph[2 * j][0],     pa1 = ph[2 * j][1];
            uint32_t pa2 = ph[2 * j + 1][0], pa3 = ph[2 * j + 1][1];
            #pragma unroll
            for (int np = 0; np < 4; np++) {
                uint32_t v0, v1, v2, v3;
                uint32_t addr = vb + (uint32_t)(16 * j + vrow) * FP_B
                              + (uint32_t)(16 * np) * 2u + voff;
                LDSM4T(v0, v1, v2, v3, addr);
                HMMA(oacc[2 * np],     pa0, pa1, pa2, pa3, v0, v1);
                HMMA(oacc[2 * np + 1], pa0, pa1, pa2, pa3, v2, v3);
            }
        }
        __syncthreads();

        // refill buffer kt&1 with tile kt+2
        if (kt + 2 < 16) {
            uint32_t kd = ksm + (uint32_t)(kt & 1) * (64 * FP_B);
            uint32_t vd = vsm + (uint32_t)(kt & 1) * (64 * FP_B);
            int g0 = (kt + 2) << 6;
            #pragma unroll
            for (int i = 0; i < 4; i++) {
                int row = r0 + 16 * i;
                cp16(kd + row * FP_B + cp * 16,
                     kbase + (size_t)(g0 + row) * (3 * EMBED) + cp * 8);
                cp16(vd + row * FP_B + cp * 16,
                     vbase + (size_t)(g0 + row) * (3 * EMBED) + cp * 8);
            }
            CP_COMMIT();
        }
    }

    // ---- epilogue ----
    float inv0 = 1.f / l0v, inv1 = 1.f / l1v;
    int row0 = q0 + 16 * warp + lr;
    __half* o0 = out + (size_t)(b * SEQ + row0) * EMBED + h * HD;
    __half* o1 = o0 + (size_t)8 * EMBED;
    #pragma unroll
    for (int n = 0; n < 8; n++) {
        *reinterpret_cast<__half2*>(o0 + 8 * n + 2 * lc) =
            __floats2half2_rn(oacc[n][0] * inv0, oacc[n][1] * inv0);
        *reinterpret_cast<__half2*>(o1 + 8 * n + 2 * lc) =
            __floats2half2_rn(oacc[n][2] * inv1, oacc[n][3] * inv1);
    }
}

// ---------------- launcher ---------------------------------------------------
extern "C" void kernel_launch(void* const* d_in, const int* in_sizes, int n_in,
                              void* d_out, int out_size)
{
    const float* x      = (const float*)d_in[0];
    const float* ln1_g  = (const float*)d_in[1];
    const float* ln1_b  = (const float*)d_in[2];
    const float* w_qkv  = (const float*)d_in[3];
    const float* b_qkv  = (const float*)d_in[4];
    const float* w_proj = (const float*)d_in[5];
    const float* b_proj = (const float*)d_in[6];
    const float* ln2_g  = (const float*)d_in[7];
    const float* ln2_b  = (const float*)d_in[8];
    const float* w_fc1  = (const float*)d_in[9];
    const float* b_fc1  = (const float*)d_in[10];
    const float* w_fc2  = (const float*)d_in[11];
    const float* b_fc2  = (const float*)d_in[12];
    float* out = (float*)d_out;

    __half *h, *qkv, *attn, *fc1, *wt;
    cudaGetSymbolAddress((void**)&h,    g_h);
    cudaGetSymbolAddress((void**)&qkv,  g_qkv);
    cudaGetSymbolAddress((void**)&attn, g_attn);
    cudaGetSymbolAddress((void**)&fc1,  g_fc1);
    cudaGetSymbolAddress((void**)&wt,   g_wt);

    cudaFuncSetAttribute(tgemm<1>, cudaFuncAttributeMaxDynamicSharedMemorySize, TGEMM_SMEM);
    cudaFuncSetAttribute(tgemm<2>, cudaFuncAttributeMaxDynamicSharedMemorySize, TGEMM_SMEM);
    cudaFuncSetAttribute(tgemm<3>, cudaFuncAttributeMaxDynamicSharedMemorySize, TGEMM_SMEM);

    __half* qkvT  = wt + WT_QKV;
    __half* projT = wt + WT_PROJ;
    __half* fc1T  = wt + WT_FC1;
    __half* fc2T  = wt + WT_FC2;

    // 0) transpose weights to [N, K] fp16 (K-major)
    transpose_kernel<<<dim3(3 * EMBED / 32, EMBED / 32),   dim3(32, 8)>>>(w_qkv,  qkvT,  EMBED,   3 * EMBED);
    transpose_kernel<<<dim3(EMBED / 32,     EMBED / 32),   dim3(32, 8)>>>(w_proj, projT, EMBED,   EMBED);
    transpose_kernel<<<dim3(MLP_DIM / 32,   EMBED / 32),   dim3(32, 8)>>>(w_fc1,  fc1T,  EMBED,   MLP_DIM);
    transpose_kernel<<<dim3(EMBED / 32,     MLP_DIM / 32), dim3(32, 8)>>>(w_fc2,  fc2T,  MLP_DIM, EMBED);

    // 1) LN1: x -> h (fp16)
    ln_kernel<<<ROWS, 256>>>(x, ln1_g, ln1_b, h);

    // 2) QKV GEMM: h @ w_qkv + b_qkv -> qkv (fp16)
    tgemm<3><<<dim3(3 * EMBED / 128, ROWS / 128), 256, TGEMM_SMEM>>>(
        h, qkvT, b_qkv, nullptr, qkv, 3 * EMBED, EMBED);

    // 3) attention -> attn (fp16, tensor cores)
    flash_mma<<<dim3(BATCH * HEADS, SEQ / 64), 128>>>(qkv, attn);

    // 4) proj + residual(x) -> out (fp32)
    tgemm<1><<<dim3(EMBED / 128, ROWS / 128), 256, TGEMM_SMEM>>>(
        attn, projT, b_proj, x, out, EMBED, EMBED);

    // 5) LN2: out -> h (fp16)
    ln_kernel<<<ROWS, 256>>>(out, ln2_g, ln2_b, h);

    // 6) FC1 + GELU: h @ w_fc1 -> fc1 (fp16)
    tgemm<2><<<dim3(MLP_DIM / 128, ROWS / 128), 256, TGEMM_SMEM>>>(
        h, fc1T, b_fc1, nullptr, fc1, MLP_DIM, EMBED);

    // 7) FC2 + residual(out) -> out (fp32, in-place elementwise safe)
    tgemm<1><<<dim3(EMBED / 128, ROWS / 128), 256, TGEMM_SMEM>>>(
        fc1, fc2T, b_fc2, out, out, EMBED, MLP_DIM);
}

// round 12
// speedup vs baseline: 8.2970x; 1.2391x over previous
#include <cuda_runtime.h>
#include <cuda_fp16.h>
#include <math.h>
#include <stdint.h>

#define EMBED 1024
#define HEADS 16
#define HD 64
#define MLP_DIM 4096
#define BATCH 8
#define SEQ 1024
#define ROWS (BATCH * SEQ)   // 8192

// ---------------- scratch (device globals: no allocation allowed) -----------
__device__ __half g_h[ROWS * EMBED];          // 16 MB (LN outputs, fp16)
__device__ __half g_qkv[ROWS * 3 * EMBED];    // 50 MB (fp16)
__device__ __half g_attn[ROWS * EMBED];       // 16 MB (fp16)
__device__ __half g_fc1[ROWS * MLP_DIM];      // 64 MB (fp16)
__device__ __half g_wt[12582912];             // 24 MB (transposed weights, fp16)

#define WT_QKV  0
#define WT_PROJ (3 * EMBED * EMBED)
#define WT_FC1  (WT_PROJ + EMBED * EMBED)
#define WT_FC2  (WT_FC1 + EMBED * MLP_DIM)

__device__ __forceinline__ void cp16(uint32_t dst, const void* src) {
    asm volatile("cp.async.cg.shared.global [%0], [%1], 16;"
                 :: "r"(dst), "l"(src) : "memory");
}
#define CP_COMMIT() asm volatile("cp.async.commit_group;" ::: "memory")
#define CP_WAIT(n)  asm volatile("cp.async.wait_group %0;" :: "n"(n) : "memory")

#define LDSM4(r0, r1, r2, r3, addr) \
    asm volatile("ldmatrix.sync.aligned.m8n8.x4.shared.b16 {%0,%1,%2,%3}, [%4];" \
                 : "=r"(r0), "=r"(r1), "=r"(r2), "=r"(r3) : "r"(addr))
#define LDSM4T(r0, r1, r2, r3, addr) \
    asm volatile("ldmatrix.sync.aligned.m8n8.x4.trans.shared.b16 {%0,%1,%2,%3}, [%4];" \
                 : "=r"(r0), "=r"(r1), "=r"(r2), "=r"(r3) : "r"(addr))

#define HMMA(d, a0, a1, a2, a3, b0, b1) \
    asm volatile("mma.sync.aligned.m16n8k16.row.col.f32.f16.f16.f32 " \
                 "{%0,%1,%2,%3}, {%4,%5,%6,%7}, {%8,%9}, {%0,%1,%2,%3};" \
                 : "+f"((d)[0]), "+f"((d)[1]), "+f"((d)[2]), "+f"((d)[3]) \
                 : "r"(a0), "r"(a1), "r"(a2), "r"(a3), "r"(b0), "r"(b1))

__device__ __forceinline__ uint32_t pack2(float x, float y) {
    __half2 h = __floats2half2_rn(x, y);
    return *reinterpret_cast<uint32_t*>(&h);
}

// ---------------- weight transpose: out[N,K] = fp16(in[K,N]^T) --------------
__global__ __launch_bounds__(256) void transpose_kernel(
    const float* __restrict__ in, __half* __restrict__ out, int K, int N)
{
    __shared__ float tile[32][33];
    int n0 = blockIdx.x * 32, k0 = blockIdx.y * 32;
    int tx = threadIdx.x, ty = threadIdx.y;   // 32 x 8
    #pragma unroll
    for (int i = 0; i < 32; i += 8)
        tile[ty + i][tx] = in[(size_t)(k0 + ty + i) * N + n0 + tx];
    __syncthreads();
    #pragma unroll
    for (int i = 0; i < 32; i += 8)
        out[(size_t)(n0 + ty + i) * K + k0 + tx] = __float2half_rn(tile[tx][ty + i]);
}

// ---------------- fp16 mma.sync GEMM: C = A[M,K] @ WT[N,K]^T ----------------
// CTA 128x128, 4 warps (2M x 2N), warp tile 64x64, m16n8k16 atoms.
// BK=32 (2 x k16), 4-stage cp.async pipeline, ONE __syncthreads per slab.
// MODE 0: +bias -> f32 | MODE 1: +bias+res -> f32 | MODE 2: +bias,GELU -> f16
// MODE 3: +bias -> f16
#define ROWH   40
#define TILE_B (128 * ROWH * 2)            // 10240 bytes per operand tile
#define NSTAGE 4
#define TGEMM_SMEM (NSTAGE * 2 * TILE_B)   // 81920 bytes

template <int MODE>
__global__ __launch_bounds__(128, 2) void tgemm(
    const __half* __restrict__ A, const __half* __restrict__ WT,
    const float* __restrict__ bias, const float* __restrict__ res,
    void* __restrict__ Cv, int N, int K)
{
    extern __shared__ char smc[];
    const uint32_t smb = (uint32_t)__cvta_generic_to_shared(smc);
    const int t = threadIdx.x;
    const int warp = t >> 5, lane = t & 31;
    const int lr = lane >> 2, lc = lane & 3;
    const int wm = warp >> 1, wn = warp & 1;     // 2 x 2
    const int m0 = blockIdx.y << 7;
    const int n0 = blockIdx.x << 7;

    float acc[4][8][4];
    #pragma unroll
    for (int m = 0; m < 4; m++)
        #pragma unroll
        for (int n = 0; n < 8; n++)
            #pragma unroll
            for (int r = 0; r < 4; r++) acc[m][n][r] = 0.f;

    const __half* Ab = A  + (size_t)m0 * K;
    const __half* Bb = WT + (size_t)n0 * K;
    const int S = K >> 5;

    // loader: thread t -> rows (t>>2)+32i (i<4), 16B chunk (t&3), both tiles
    const int lrow  = t >> 2;    // 0..31
    const int lpart = t & 3;

    const int rA  = lane & 15;
    const int khA = (lane >> 4) << 3;
    const int rB  = (lane & 7) + ((lane >> 4) << 3);
    const int khB = ((lane >> 3) & 1) << 3;

    #define STAGE_LOAD(buf, kc)                                                  \
        do {                                                                     \
            uint32_t sa = smb + (uint32_t)(buf) * (2 * TILE_B);                  \
            uint32_t sb = sa + TILE_B;                                           \
            _Pragma("unroll")                                                    \
            for (int i = 0; i < 4; i++) {                                        \
                int rw = lrow + 32 * i;                                          \
                cp16(sa + rw * 80 + lpart * 16,                                  \
                     Ab + (size_t)rw * K + (kc) + lpart * 8);                    \
                cp16(sb + rw * 80 + lpart * 16,                                  \
                     Bb + (size_t)rw * K + (kc) + lpart * 8);                    \
            }                                                                    \
        } while (0)

    STAGE_LOAD(0, 0);
    CP_COMMIT();
    if (S > 1) { STAGE_LOAD(1, 32); CP_COMMIT(); }
    if (S > 2) { STAGE_LOAD(2, 64); CP_COMMIT(); }

    int buf = 0;
    for (int s = 0; s < S; s++) {
        if (s + 2 < S)      { CP_WAIT(2); }
        else if (s + 1 < S) { CP_WAIT(1); }
        else                { CP_WAIT(0); }
        __syncthreads();

        const uint32_t As = smb + (uint32_t)buf * (2 * TILE_B);
        const uint32_t Bs = As + TILE_B;
        #pragma unroll
        for (int kk = 0; kk < 2; kk++) {
            uint32_t a[4][4], b[8][2];
            #pragma unroll
            for (int m = 0; m < 4; m++) {
                uint32_t addr = As + (uint32_t)(wm * 64 + m * 16 + rA) * 80u
                              + (uint32_t)(kk * 16 + khA) * 2u;
                LDSM4(a[m][0], a[m][1], a[m][2], a[m][3], addr);
            }
            #pragma unroll
            for (int np = 0; np < 4; np++) {
                uint32_t addr = Bs + (uint32_t)(wn * 64 + np * 16 + rB) * 80u
                              + (uint32_t)(kk * 16 + khB) * 2u;
                LDSM4(b[2 * np][0], b[2 * np][1], b[2 * np + 1][0], b[2 * np + 1][1], addr);
            }
            #pragma unroll
            for (int m = 0; m < 4; m++)
                #pragma unroll
                for (int n = 0; n < 8; n++)
                    HMMA(acc[m][n], a[m][0], a[m][1], a[m][2], a[m][3],
                         b[n][0], b[n][1]);
        }
        // NOTE: no second barrier. Next load targets buf+3 (mod 4), which no
        // thread can read or overwrite until after the NEXT iteration-top
        // barrier, so the single barrier per slab is sufficient.
        if (s + 3 < S) {
            int nb = buf + 3; if (nb >= NSTAGE) nb -= NSTAGE;
            STAGE_LOAD(nb, (s + 3) << 5);
            CP_COMMIT();
        }
        buf = buf + 1; if (buf == NSTAGE) buf = 0;
    }
    #undef STAGE_LOAD

    // ---------------- epilogue ----------------
    const int rb = m0 + wm * 64;
    const int cb = n0 + wn * 64;
    #pragma unroll
    for (int m = 0; m < 4; m++) {
        #pragma unroll
        for (int n = 0; n < 8; n++) {
            int r = rb + m * 16 + lr;
            int c = cb + n * 8 + lc * 2;
            float2 bv = *reinterpret_cast<const float2*>(bias + c);
            #pragma unroll
            for (int half_ = 0; half_ < 2; half_++) {
                int rr = r + half_ * 8;
                float o0 = acc[m][n][2 * half_ + 0] + bv.x;
                float o1 = acc[m][n][2 * half_ + 1] + bv.y;
                size_t off = (size_t)rr * N + c;
                if (MODE == 1) {
                    float2 rv = *reinterpret_cast<const float2*>(res + off);
                    o0 += rv.x; o1 += rv.y;
                }
                if (MODE == 2) {
                    o0 = 0.5f * o0 * (1.0f + erff(o0 * 0.70710678118654752f));
                    o1 = 0.5f * o1 * (1.0f + erff(o1 * 0.70710678118654752f));
                }
                if (MODE == 2 || MODE == 3) {
                    *reinterpret_cast<__half2*>((__half*)Cv + off) =
                        __floats2half2_rn(o0, o1);
                } else {
                    *reinterpret_cast<float2*>((float*)Cv + off) = make_float2(o0, o1);
                }
            }
        }
    }
}

// ---------------- LayerNorm: one block per row (fp16 output) ----------------
__global__ __launch_bounds__(256) void ln_kernel(
    const float* __restrict__ x, const float* __restrict__ g,
    const float* __restrict__ b, __half* __restrict__ out)
{
    int row = blockIdx.x;
    int t = threadIdx.x;
    const float4* xr = reinterpret_cast<const float4*>(x + (size_t)row * EMBED);
    float4 v = xr[t];
    float s  = v.x + v.y + v.z + v.w;
    float ss = v.x * v.x + v.y * v.y + v.z * v.z + v.w * v.w;
    #pragma unroll
    for (int o = 16; o > 0; o >>= 1) {
        s  += __shfl_xor_sync(0xffffffffu, s,  o);
        ss += __shfl_xor_sync(0xffffffffu, ss, o);
    }
    __shared__ float sm[8], sm2[8];
    int w = t >> 5, l = t & 31;
    if (l == 0) { sm[w] = s; sm2[w] = ss; }
    __syncthreads();
    float tot = 0.f, tot2 = 0.f;
    #pragma unroll
    for (int i = 0; i < 8; i++) { tot += sm[i]; tot2 += sm2[i]; }
    float mu   = tot * (1.0f / EMBED);
    float var  = tot2 * (1.0f / EMBED) - mu * mu;
    float rstd = rsqrtf(var + 1e-5f);
    float4 gg = reinterpret_cast<const float4*>(g)[t];
    float4 bb = reinterpret_cast<const float4*>(b)[t];
    __half2* op = reinterpret_cast<__half2*>(out + (size_t)row * EMBED);
    op[2 * t + 0] = __floats2half2_rn((v.x - mu) * rstd * gg.x + bb.x,
                                      (v.y - mu) * rstd * gg.y + bb.y);
    op[2 * t + 1] = __floats2half2_rn((v.z - mu) * rstd * gg.z + bb.z,
                                      (v.w - mu) * rstd * gg.w + bb.w);
}

// ---------------- Flash attention, fp16 tensor cores (FA2 style) ------------
#define FPITCH 72            // halves per smem row
#define FP_B   (FPITCH * 2)  // 144 bytes

__global__ __launch_bounds__(128) void flash_mma(
    const __half* __restrict__ qkv, __half* __restrict__ out)
{
    __shared__ __half Qs[64 * FPITCH];
    __shared__ __half Ks[2][64 * FPITCH];
    __shared__ __half Vs[2][64 * FPITCH];

    const int bh = blockIdx.x;
    const int b = bh >> 4, h = bh & 15;
    const int q0 = blockIdx.y << 6;
    const int t = threadIdx.x;
    const int warp = t >> 5, lane = t & 31;
    const int lr = lane >> 2, lc = lane & 3;

    const __half* base  = qkv + (size_t)b * SEQ * (3 * EMBED) + h * HD;
    const __half* kbase = base + EMBED;
    const __half* vbase = base + 2 * EMBED;

    const int r0 = t >> 3;   // 0..15
    const int cp = t & 7;    // 0..7

    const uint32_t qsm = (uint32_t)__cvta_generic_to_shared(Qs);
    const uint32_t ksm = (uint32_t)__cvta_generic_to_shared(Ks);
    const uint32_t vsm = (uint32_t)__cvta_generic_to_shared(Vs);

    // group 0: Q + K0 + V0
    #pragma unroll
    for (int i = 0; i < 4; i++) {
        int row = r0 + 16 * i;
        cp16(qsm + row * FP_B + cp * 16,
             base  + (size_t)(q0 + row) * (3 * EMBED) + cp * 8);
        cp16(ksm + row * FP_B + cp * 16,
             kbase + (size_t)row * (3 * EMBED) + cp * 8);
        cp16(vsm + row * FP_B + cp * 16,
             vbase + (size_t)row * (3 * EMBED) + cp * 8);
    }
    CP_COMMIT();
    // group 1: K1 + V1
    #pragma unroll
    for (int i = 0; i < 4; i++) {
        int row = r0 + 16 * i;
        cp16(ksm + 64 * FP_B + row * FP_B + cp * 16,
             kbase + (size_t)(64 + row) * (3 * EMBED) + cp * 8);
        cp16(vsm + 64 * FP_B + row * FP_B + cp * 16,
             vbase + (size_t)(64 + row) * (3 * EMBED) + cp * 8);
    }
    CP_COMMIT();

    float oacc[8][4];
    #pragma unroll
    for (int n = 0; n < 8; n++)
        #pragma unroll
        for (int c = 0; c < 4; c++) oacc[n][c] = 0.f;
    float m0v = -1e30f, m1v = -1e30f, l0v = 0.f, l1v = 0.f;

    const uint32_t qaddr0 = qsm + (uint32_t)(16 * warp + (lane & 15)) * FP_B
                          + (uint32_t)((lane >> 4) << 3) * 2u;
    const int rB  = (lane & 7) + ((lane >> 4) << 3);
    const int khB = ((lane >> 3) & 1) << 3;
    const uint32_t vrow = (uint32_t)(lane & 15);
    const uint32_t voff = (uint32_t)((lane >> 4) << 3) * 2u;

    for (int kt = 0; kt < 16; kt++) {
        if (kt < 15) { CP_WAIT(1); } else { CP_WAIT(0); }
        __syncthreads();
        const uint32_t kb = ksm + (uint32_t)(kt & 1) * (64 * FP_B);
        const uint32_t vb = vsm + (uint32_t)(kt & 1) * (64 * FP_B);

        // ---- S = Q @ K^T ----
        float sacc[8][4];
        #pragma unroll
        for (int n = 0; n < 8; n++)
            #pragma unroll
            for (int c = 0; c < 4; c++) sacc[n][c] = 0.f;

        #pragma unroll
        for (int kk = 0; kk < 4; kk++) {
            uint32_t a0, a1, a2, a3;
            LDSM4(a0, a1, a2, a3, qaddr0 + (uint32_t)kk * 32u);
            uint32_t bk[8][2];
            #pragma unroll
            for (int np = 0; np < 4; np++) {
                uint32_t addr = kb + (uint32_t)(16 * np + rB) * FP_B
                              + (uint32_t)(16 * kk + khB) * 2u;
                LDSM4(bk[2 * np][0], bk[2 * np][1],
                      bk[2 * np + 1][0], bk[2 * np + 1][1], addr);
            }
            #pragma unroll
            for (int n = 0; n < 8; n++)
                HMMA(sacc[n], a0, a1, a2, a3, bk[n][0], bk[n][1]);
        }

        // ---- online softmax (rows lr and lr+8; a row = 4 lanes via lc) ----
        #pragma unroll
        for (int n = 0; n < 8; n++)
            #pragma unroll
            for (int c = 0; c < 4; c++) sacc[n][c] *= 0.125f;

        float mx0 = -1e30f, mx1 = -1e30f;
        #pragma unroll
        for (int n = 0; n < 8; n++) {
            mx0 = fmaxf(mx0, fmaxf(sacc[n][0], sacc[n][1]));
            mx1 = fmaxf(mx1, fmaxf(sacc[n][2], sacc[n][3]));
        }
        mx0 = fmaxf(mx0, __shfl_xor_sync(0xffffffffu, mx0, 1));
        mx0 = fmaxf(mx0, __shfl_xor_sync(0xffffffffu, mx0, 2));
        mx1 = fmaxf(mx1, __shfl_xor_sync(0xffffffffu, mx1, 1));
        mx1 = fmaxf(mx1, __shfl_xor_sync(0xffffffffu, mx1, 2));

        float mn0 = fmaxf(m0v, mx0), mn1 = fmaxf(m1v, mx1);
        float c0 = __expf(m0v - mn0), c1 = __expf(m1v - mn1);

        uint32_t ph[8][2];
        float ls0 = 0.f, ls1 = 0.f;
        #pragma unroll
        for (int n = 0; n < 8; n++) {
            float p0 = __expf(sacc[n][0] - mn0);
            float p1 = __expf(sacc[n][1] - mn0);
            float p2 = __expf(sacc[n][2] - mn1);
            float p3 = __expf(sacc[n][3] - mn1);
            ls0 += p0 + p1;
            ls1 += p2 + p3;
            ph[n][0] = pack2(p0, p1);
            ph[n][1] = pack2(p2, p3);
        }
        ls0 += __shfl_xor_sync(0xffffffffu, ls0, 1);
        ls0 += __shfl_xor_sync(0xffffffffu, ls0, 2);
        ls1 += __shfl_xor_sync(0xffffffffu, ls1, 1);
        ls1 += __shfl_xor_sync(0xffffffffu, ls1, 2);

        l0v = l0v * c0 + ls0;
        l1v = l1v * c1 + ls1;
        m0v = mn0; m1v = mn1;
        #pragma unroll
        for (int n = 0; n < 8; n++) {
            oacc[n][0] *= c0; oacc[n][1] *= c0;
            oacc[n][2] *= c1; oacc[n][3] *= c1;
        }

        // ---- O += P @ V ----  (A frags straight from score accumulators)
        #pragma unroll
        for (int j = 0; j < 4; j++) {
            uint32_t pa0 = ph[2 * j][0],     pa1 = ph[2 * j][1];
            uint32_t pa2 = ph[2 * j + 1][0], pa3 = ph[2 * j + 1][1];
            #pragma unroll
            for (int np = 0; np < 4; np++) {
                uint32_t v0, v1, v2, v3;
                uint32_t addr = vb + (uint32_t)(16 * j + vrow) * FP_B
                              + (uint32_t)(16 * np) * 2u + voff;
                LDSM4T(v0, v1, v2, v3, addr);
                HMMA(oacc[2 * np],     pa0, pa1, pa2, pa3, v0, v1);
                HMMA(oacc[2 * np + 1], pa0, pa1, pa2, pa3, v2, v3);
            }
        }
        __syncthreads();

        // refill buffer kt&1 with tile kt+2
        if (kt + 2 < 16) {
            uint32_t kd = ksm + (uint32_t)(kt & 1) * (64 * FP_B);
            uint32_t vd = vsm + (uint32_t)(kt & 1) * (64 * FP_B);
            int g0 = (kt + 2) << 6;
            #pragma unroll
            for (int i = 0; i < 4; i++) {
                int row = r0 + 16 * i;
                cp16(kd + row * FP_B + cp * 16,
                     kbase + (size_t)(g0 + row) * (3 * EMBED) + cp * 8);
                cp16(vd + row * FP_B + cp * 16,
                     vbase + (size_t)(g0 + row) * (3 * EMBED) + cp * 8);
            }
            CP_COMMIT();
        }
    }

    // ---- epilogue ----
    float inv0 = 1.f / l0v, inv1 = 1.f / l1v;
    int row0 = q0 + 16 * warp + lr;
    __half* o0 = out + (size_t)(b * SEQ + row0) * EMBED + h * HD;
    __half* o1 = o0 + (size_t)8 * EMBED;
    #pragma unroll
    for (int n = 0; n < 8; n++) {
        *reinterpret_cast<__half2*>(o0 + 8 * n + 2 * lc) =
            __floats2half2_rn(oacc[n][0] * inv0, oacc[n][1] * inv0);
        *reinterpret_cast<__half2*>(o1 + 8 * n + 2 * lc) =
            __floats2half2_rn(oacc[n][2] * inv1, oacc[n][3] * inv1);
    }
}

// ---------------- launcher ---------------------------------------------------
extern "C" void kernel_launch(void* const* d_in, const int* in_sizes, int n_in,
                              void* d_out, int out_size)
{
    const float* x      = (const float*)d_in[0];
    const float* ln1_g  = (const float*)d_in[1];
    const float* ln1_b  = (const float*)d_in[2];
    const float* w_qkv  = (const float*)d_in[3];
    const float* b_qkv  = (const float*)d_in[4];
    const float* w_proj = (const float*)d_in[5];
    const float* b_proj = (const float*)d_in[6];
    const float* ln2_g  = (const float*)d_in[7];
    const float* ln2_b  = (const float*)d_in[8];
    const float* w_fc1  = (const float*)d_in[9];
    const float* b_fc1  = (const float*)d_in[10];
    const float* w_fc2  = (const float*)d_in[11];
    const float* b_fc2  = (const float*)d_in[12];
    float* out = (float*)d_out;

    __half *h, *qkv, *attn, *fc1, *wt;
    cudaGetSymbolAddress((void**)&h,    g_h);
    cudaGetSymbolAddress((void**)&qkv,  g_qkv);
    cudaGetSymbolAddress((void**)&attn, g_attn);
    cudaGetSymbolAddress((void**)&fc1,  g_fc1);
    cudaGetSymbolAddress((void**)&wt,   g_wt);

    cudaFuncSetAttribute(tgemm<1>, cudaFuncAttributeMaxDynamicSharedMemorySize, TGEMM_SMEM);
    cudaFuncSetAttribute(tgemm<2>, cudaFuncAttributeMaxDynamicSharedMemorySize, TGEMM_SMEM);
    cudaFuncSetAttribute(tgemm<3>, cudaFuncAttributeMaxDynamicSharedMemorySize, TGEMM_SMEM);

    __half* qkvT  = wt + WT_QKV;
    __half* projT = wt + WT_PROJ;
    __half* fc1T  = wt + WT_FC1;
    __half* fc2T  = wt + WT_FC2;

    // 0) transpose weights to [N, K] fp16 (K-major)
    transpose_kernel<<<dim3(3 * EMBED / 32, EMBED / 32),   dim3(32, 8)>>>(w_qkv,  qkvT,  EMBED,   3 * EMBED);
    transpose_kernel<<<dim3(EMBED / 32,     EMBED / 32),   dim3(32, 8)>>>(w_proj, projT, EMBED,   EMBED);
    transpose_kernel<<<dim3(MLP_DIM / 32,   EMBED / 32),   dim3(32, 8)>>>(w_fc1,  fc1T,  EMBED,   MLP_DIM);
    transpose_kernel<<<dim3(EMBED / 32,     MLP_DIM / 32), dim3(32, 8)>>>(w_fc2,  fc2T,  MLP_DIM, EMBED);

    // 1) LN1: x -> h (fp16)
    ln_kernel<<<ROWS, 256>>>(x, ln1_g, ln1_b, h);

    // 2) QKV GEMM: h @ w_qkv + b_qkv -> qkv (fp16)
    tgemm<3><<<dim3(3 * EMBED / 128, ROWS / 128), 128, TGEMM_SMEM>>>(
        h, qkvT, b_qkv, nullptr, qkv, 3 * EMBED, EMBED);

    // 3) attention -> attn (fp16, tensor cores)
    flash_mma<<<dim3(BATCH * HEADS, SEQ / 64), 128>>>(qkv, attn);

    // 4) proj + residual(x) -> out (fp32)
    tgemm<1><<<dim3(EMBED / 128, ROWS / 128), 128, TGEMM_SMEM>>>(
        attn, projT, b_proj, x, out, EMBED, EMBED);

    // 5) LN2: out -> h (fp16)
    ln_kernel<<<ROWS, 256>>>(out, ln2_g, ln2_b, h);

    // 6) FC1 + GELU: h @ w_fc1 -> fc1 (fp16)
    tgemm<2><<<dim3(MLP_DIM / 128, ROWS / 128), 128, TGEMM_SMEM>>>(
        h, fc1T, b_fc1, nullptr, fc1, MLP_DIM, EMBED);

    // 7) FC2 + residual(out) -> out (fp32, in-place elementwise safe)
    tgemm<1><<<dim3(EMBED / 128, ROWS / 128), 128, TGEMM_SMEM>>>(
        fc1, fc2T, b_fc2, out, out, EMBED, MLP_DIM);
}